// round 1
// baseline (speedup 1.0000x reference)
#include <cuda_runtime.h>
#include <math.h>

// ---------------- problem constants (hardcoded shapes) ----------------
#define BB   4
#define SS   1024
#define EE   1024
#define HH   16
#define KDIM 64
#define VDIM 64
#define DD   4096
#define MTOK 4096            // B*S tokens
#define LNEPS 1e-5f

// ---------------- device scratch (static globals; no allocations) ----------------
__device__ float g_h [MTOK * EE];                 // LN output (reused for LN1 and LN2)
__device__ float g_q [HH * MTOK * KDIM];          // [H][B*S][64]
__device__ float g_k [HH * MTOK * KDIM];
__device__ float g_v [HH * MTOK * VDIM];
__device__ float g_sc[HH * BB * SS * SS];         // [64][1024][1024] scores/probs (256 MB)
__device__ float g_ot[HH * MTOK * VDIM];          // attention out, head-major
__device__ float g_oc[MTOK * EE];                 // attention out, concat layout
__device__ float g_x1[MTOK * EE];                 // x + attn
__device__ float g_f1[MTOK * DD];
__device__ float g_f2[MTOK * DD];

// ---------------- LayerNorm: one block per row, row cached in smem ----------------
__global__ __launch_bounds__(256) void ln_kernel(
    const float* __restrict__ x, const float* __restrict__ g,
    const float* __restrict__ b, float* __restrict__ out)
{
    __shared__ float row[EE];
    __shared__ float red[256];
    const int r = blockIdx.x;
    const int t = threadIdx.x;
    const float* xr = x + (size_t)r * EE;

    float s = 0.f;
    for (int i = t; i < EE; i += 256) { float v = xr[i]; row[i] = v; s += v; }
    red[t] = s; __syncthreads();
    for (int o = 128; o > 0; o >>= 1) { if (t < o) red[t] += red[t + o]; __syncthreads(); }
    const float mean = red[0] * (1.0f / EE);
    __syncthreads();

    float vs = 0.f;
    for (int i = t; i < EE; i += 256) { float d = row[i] - mean; vs += d * d; }
    red[t] = vs; __syncthreads();
    for (int o = 128; o > 0; o >>= 1) { if (t < o) red[t] += red[t + o]; __syncthreads(); }
    const float rstd = rsqrtf(red[0] * (1.0f / EE) + LNEPS);

    float* orow = out + (size_t)r * EE;
    for (int i = t; i < EE; i += 256)
        orow[i] = (row[i] - mean) * rstd * g[i] + b[i];
}

// ---------------- Generic tiled fp32 GEMM ----------------
// C[M,N] = A[M,K] * B (+bias)(+res)(relu), optionally batched over blockIdx.z.
// TRB: B is [N,K] row-major (i.e., compute A * B^T).
template<int BM, int BN, int BK, int TM, int TN, bool TRB, bool BIAS, bool RELU, bool RES>
__global__ __launch_bounds__(256) void gemm_kernel(
    const float* __restrict__ A, const float* __restrict__ Bm,
    const float* __restrict__ bias, const float* __restrict__ res,
    float* __restrict__ C, int M, int N, int K,
    long long sA, long long sB, long long sC)
{
    static_assert((BM / TM) * (BN / TN) == 256, "256 threads");
    __shared__ float As[BK][BM];
    __shared__ float Bs[BK][BN];

    const int z = blockIdx.z;
    A += (long long)z * sA;
    Bm += (long long)z * sB;
    C += (long long)z * sC;
    const float* R = RES ? (res + (long long)z * sC) : nullptr;

    const int m0 = blockIdx.y * BM;
    const int n0 = blockIdx.x * BN;
    const int t  = threadIdx.x;
    const int tx = t % (BN / TN);
    const int ty = t / (BN / TN);

    float acc[TM][TN];
#pragma unroll
    for (int i = 0; i < TM; i++)
#pragma unroll
        for (int j = 0; j < TN; j++) acc[i][j] = 0.f;

    for (int k0 = 0; k0 < K; k0 += BK) {
        // ---- load A tile (transposed into As[k][m]) ----
        constexpr int AF4 = BM * BK / (4 * 256);
#pragma unroll
        for (int i = 0; i < AF4; i++) {
            int idx = t + i * 256;
            int row = idx / (BK / 4);
            int k4  = idx % (BK / 4);
            float4 v = *(const float4*)(A + (long long)(m0 + row) * K + k0 + k4 * 4);
            As[k4 * 4 + 0][row] = v.x;
            As[k4 * 4 + 1][row] = v.y;
            As[k4 * 4 + 2][row] = v.z;
            As[k4 * 4 + 3][row] = v.w;
        }
        // ---- load B tile ----
        if (TRB) {
            constexpr int BF4 = BN * BK / (4 * 256);
#pragma unroll
            for (int i = 0; i < BF4; i++) {
                int idx = t + i * 256;
                int n  = idx / (BK / 4);
                int k4 = idx % (BK / 4);
                float4 v = *(const float4*)(Bm + (long long)(n0 + n) * K + k0 + k4 * 4);
                Bs[k4 * 4 + 0][n] = v.x;
                Bs[k4 * 4 + 1][n] = v.y;
                Bs[k4 * 4 + 2][n] = v.z;
                Bs[k4 * 4 + 3][n] = v.w;
            }
        } else {
            constexpr int BF4 = BK * BN / (4 * 256);
#pragma unroll
            for (int i = 0; i < BF4; i++) {
                int idx = t + i * 256;
                int row = idx / (BN / 4);
                int c4  = idx % (BN / 4);
                *(float4*)(&Bs[row][c4 * 4]) =
                    *(const float4*)(Bm + (long long)(k0 + row) * N + n0 + c4 * 4);
            }
        }
        __syncthreads();

        // ---- compute ----
#pragma unroll
        for (int kk = 0; kk < BK; kk++) {
            float a[TM], bfr[TN];
#pragma unroll
            for (int i = 0; i < TM; i += 4)
                *(float4*)(&a[i]) = *(const float4*)(&As[kk][ty * TM + i]);
#pragma unroll
            for (int j = 0; j < TN; j += 4)
                *(float4*)(&bfr[j]) = *(const float4*)(&Bs[kk][tx * TN + j]);
#pragma unroll
            for (int i = 0; i < TM; i++)
#pragma unroll
                for (int j = 0; j < TN; j++)
                    acc[i][j] += a[i] * bfr[j];
        }
        __syncthreads();
    }

    // ---- epilogue ----
#pragma unroll
    for (int i = 0; i < TM; i++) {
        const int row = m0 + ty * TM + i;
        const long long base = (long long)row * N + n0 + tx * TN;
#pragma unroll
        for (int j0 = 0; j0 < TN; j0 += 4) {
            float4 v;
            v.x = acc[i][j0 + 0];
            v.y = acc[i][j0 + 1];
            v.z = acc[i][j0 + 2];
            v.w = acc[i][j0 + 3];
            if (BIAS) {
                const int c = n0 + tx * TN + j0;
                v.x += bias[c + 0]; v.y += bias[c + 1];
                v.z += bias[c + 2]; v.w += bias[c + 3];
            }
            if (RES) {
                float4 rv = *(const float4*)(R + base + j0);
                v.x += rv.x; v.y += rv.y; v.z += rv.z; v.w += rv.w;
            }
            if (RELU) {
                v.x = fmaxf(v.x, 0.f); v.y = fmaxf(v.y, 0.f);
                v.z = fmaxf(v.z, 0.f); v.w = fmaxf(v.w, 0.f);
            }
            *(float4*)(C + base + j0) = v;
        }
    }
}

// ---------------- causal softmax over raw scores (scale + faithful mask) ----------------
// row r: head-batch hb = r / S, query index i = r % S. Valid keys j <= i.
// Faithful to jnp.where(tril(scores)==0, -inf, scores): an exactly-zero kept
// score is also masked.
__global__ __launch_bounds__(256) void softmax_kernel(float* __restrict__ sc)
{
    __shared__ float row[SS];
    __shared__ float red[256];
    const long long r = blockIdx.x;
    const int i = (int)(r % SS);
    const int n = i + 1;                 // number of unmasked keys
    float* p = sc + r * (long long)SS;
    const int t = threadIdx.x;
    const float scale = 0.125f;          // KD^-0.5 = 1/8

    float m = -INFINITY;
    for (int j = t; j < n; j += 256) {
        float raw = p[j];
        float s = (raw == 0.f) ? -INFINITY : raw * scale;
        row[j] = s;
        m = fmaxf(m, s);
    }
    red[t] = m; __syncthreads();
    for (int o = 128; o > 0; o >>= 1) { if (t < o) red[t] = fmaxf(red[t], red[t + o]); __syncthreads(); }
    m = red[0]; __syncthreads();

    float ssum = 0.f;
    for (int j = t; j < n; j += 256) {
        float e = __expf(row[j] - m);
        row[j] = e;
        ssum += e;
    }
    red[t] = ssum; __syncthreads();
    for (int o = 128; o > 0; o >>= 1) { if (t < o) red[t] += red[t + o]; __syncthreads(); }
    const float inv = 1.f / red[0];

    for (int j = t; j < n; j += 256) p[j] = row[j] * inv;
    for (int j = t; j < SS; j += 256) if (j >= n) p[j] = 0.f;  // masked -> prob 0
}

// ---------------- head-major -> concat reorder ----------------
// in[((h*BB+b)*SS+s)*VDIM+vd] -> out[(b*SS+s)*EE + h*VDIM + vd]
__global__ __launch_bounds__(256) void reorder_kernel(
    const float* __restrict__ in, float* __restrict__ out)
{
    int idx = blockIdx.x * 256 + threadIdx.x;
    int vd = idx % VDIM;
    int rest = idx / VDIM;
    int s = rest % SS; rest /= SS;
    int b = rest % BB;
    int h = rest / BB;
    out[((size_t)(b * SS + s)) * EE + h * VDIM + vd] = in[idx];
}

// ---------------- launcher ----------------
extern "C" void kernel_launch(void* const* d_in, const int* in_sizes, int n_in,
                              void* d_out, int out_size)
{
    (void)in_sizes; (void)n_in; (void)out_size;
    const float* x      = (const float*)d_in[0];
    const float* ln1_g  = (const float*)d_in[1];
    const float* ln1_b  = (const float*)d_in[2];
    const float* Wq     = (const float*)d_in[3];
    const float* Wk     = (const float*)d_in[4];
    const float* Wv     = (const float*)d_in[5];
    const float* proj_W = (const float*)d_in[6];
    const float* proj_b = (const float*)d_in[7];
    const float* ln2_g  = (const float*)d_in[8];
    const float* ln2_b  = (const float*)d_in[9];
    const float* fin_W  = (const float*)d_in[10];
    const float* fin_b  = (const float*)d_in[11];
    const float* hid_W  = (const float*)d_in[12];
    const float* hid_b  = (const float*)d_in[13];
    const float* fout_W = (const float*)d_in[14];
    const float* fout_b = (const float*)d_in[15];
    float* out = (float*)d_out;

    float *h, *q, *k, *v, *sc, *ot, *oc, *x1, *f1, *f2;
    cudaGetSymbolAddress((void**)&h,  g_h);
    cudaGetSymbolAddress((void**)&q,  g_q);
    cudaGetSymbolAddress((void**)&k,  g_k);
    cudaGetSymbolAddress((void**)&v,  g_v);
    cudaGetSymbolAddress((void**)&sc, g_sc);
    cudaGetSymbolAddress((void**)&ot, g_ot);
    cudaGetSymbolAddress((void**)&oc, g_oc);
    cudaGetSymbolAddress((void**)&x1, g_x1);
    cudaGetSymbolAddress((void**)&f1, g_f1);
    cudaGetSymbolAddress((void**)&f2, g_f2);

    // 1. LN1: x -> h
    ln_kernel<<<MTOK, 256>>>(x, ln1_g, ln1_b, h);

    // 2. QKV projections: batched over H (z=16). C[h][t][kd]
    {
        dim3 grid(KDIM / 64, MTOK / 128, HH);
        gemm_kernel<128, 64, 16, 8, 4, false, false, false, false><<<grid, 256>>>(
            h, Wq, nullptr, nullptr, q, MTOK, KDIM, EE,
            0LL, (long long)EE * KDIM, (long long)MTOK * KDIM);
        gemm_kernel<128, 64, 16, 8, 4, false, false, false, false><<<grid, 256>>>(
            h, Wk, nullptr, nullptr, k, MTOK, KDIM, EE,
            0LL, (long long)EE * KDIM, (long long)MTOK * KDIM);
        gemm_kernel<128, 64, 16, 8, 4, false, false, false, false><<<grid, 256>>>(
            h, Wv, nullptr, nullptr, v, MTOK, VDIM, EE,
            0LL, (long long)EE * VDIM, (long long)MTOK * VDIM);
    }

    // 3. scores = q @ k^T, batched over hb (z=64)
    {
        dim3 grid(SS / 128, SS / 128, HH * BB);
        gemm_kernel<128, 128, 8, 8, 8, true, false, false, false><<<grid, 256>>>(
            q, k, nullptr, nullptr, sc, SS, SS, KDIM,
            (long long)SS * KDIM, (long long)SS * KDIM, (long long)SS * SS);
    }

    // 4. causal scale+mask+softmax in place
    softmax_kernel<<<HH * BB * SS, 256>>>(sc);

    // 5. O = P @ V, batched over hb (z=64), head-major output
    {
        dim3 grid(VDIM / 64, SS / 128, HH * BB);
        gemm_kernel<128, 64, 16, 8, 4, false, false, false, false><<<grid, 256>>>(
            sc, v, nullptr, nullptr, ot, SS, VDIM, SS,
            (long long)SS * SS, (long long)SS * VDIM, (long long)SS * VDIM);
    }

    // 6. concat heads
    reorder_kernel<<<(HH * MTOK * VDIM) / 256, 256>>>(ot, oc);

    // 7. x1 = x + oc @ proj_W + proj_b
    {
        dim3 grid(EE / 128, MTOK / 128, 1);
        gemm_kernel<128, 128, 8, 8, 8, false, true, false, true><<<grid, 256>>>(
            oc, proj_W, proj_b, x, x1, MTOK, EE, EE, 0LL, 0LL, 0LL);
    }

    // 8. LN2: x1 -> h (reuse)
    ln_kernel<<<MTOK, 256>>>(x1, ln2_g, ln2_b, h);

    // 9. f1 = relu(h @ fin_W + fin_b)
    {
        dim3 grid(DD / 128, MTOK / 128, 1);
        gemm_kernel<128, 128, 8, 8, 8, false, true, true, false><<<grid, 256>>>(
            h, fin_W, fin_b, nullptr, f1, MTOK, DD, EE, 0LL, 0LL, 0LL);
    }

    // 10/11. hidden layers: f1 -> f2 -> f1
    {
        dim3 grid(DD / 128, MTOK / 128, 1);
        gemm_kernel<128, 128, 8, 8, 8, false, true, true, false><<<grid, 256>>>(
            f1, hid_W, hid_b, nullptr, f2, MTOK, DD, DD, 0LL, 0LL, 0LL);
        gemm_kernel<128, 128, 8, 8, 8, false, true, true, false><<<grid, 256>>>(
            f2, hid_W + (long long)DD * DD, hid_b + DD, nullptr, f1,
            MTOK, DD, DD, 0LL, 0LL, 0LL);
    }

    // 12. out = x1 + f1 @ fout_W + fout_b
    {
        dim3 grid(EE / 128, MTOK / 128, 1);
        gemm_kernel<128, 128, 8, 8, 8, false, true, false, true><<<grid, 256>>>(
            f1, fout_W, fout_b, x1, out, MTOK, EE, DD, 0LL, 0LL, 0LL);
    }
}

// round 5
// speedup vs baseline: 2.6148x; 2.6148x over previous
#include <cuda_runtime.h>
#include <cuda_bf16.h>
#include <math.h>
#include <stdint.h>

// ---------------- problem constants ----------------
#define BB   4
#define SS   1024
#define EE   1024
#define HH   16
#define KDIM 64
#define VDIM 64
#define DD   4096
#define MTOK 4096            // B*S tokens
#define LNEPS 1e-5f

// ---------------- device scratch (static globals; no allocations) ----------------
__device__ float g_h [MTOK * EE];
__device__ float g_q [HH * MTOK * KDIM];
__device__ float g_k [HH * MTOK * KDIM];
__device__ float g_v [HH * MTOK * VDIM];
__device__ float g_sc[(size_t)HH * BB * SS * SS];   // 256 MB scores/probs
__device__ float g_ot[HH * MTOK * VDIM];
__device__ float g_oc[MTOK * EE];
__device__ float g_x1[MTOK * EE];
__device__ float g_f1[(size_t)MTOK * DD];
__device__ float g_f2[(size_t)MTOK * DD];
// bf16 split buffers
__device__ __nv_bfloat16 g_ah[(size_t)MTOK * DD];      // activations hi
__device__ __nv_bfloat16 g_al[(size_t)MTOK * DD];      // activations lo
__device__ __nv_bfloat16 g_bh[(size_t)DD * DD];        // weights^T hi
__device__ __nv_bfloat16 g_bl[(size_t)DD * DD];        // weights^T lo
__device__ __nv_bfloat16 g_qh[HH * MTOK * KDIM];
__device__ __nv_bfloat16 g_ql[HH * MTOK * KDIM];
__device__ __nv_bfloat16 g_kh[HH * MTOK * KDIM];
__device__ __nv_bfloat16 g_kl[HH * MTOK * KDIM];
__device__ __nv_bfloat16 g_vth[HH * MTOK * VDIM];      // V^T per head-batch
__device__ __nv_bfloat16 g_vtl[HH * MTOK * VDIM];
__device__ __nv_bfloat16 g_ph[(size_t)HH * BB * SS * SS];
__device__ __nv_bfloat16 g_pl[(size_t)HH * BB * SS * SS];

// ================= low-level helpers (sm_80+ base-target PTX only) =================
__device__ __forceinline__ uint32_t smem_to_u32(const void* p) {
    uint32_t a;
    asm("{ .reg .u64 t; cvta.to.shared.u64 t, %1; cvt.u32.u64 %0, t; }"
        : "=r"(a) : "l"(p));
    return a;
}
__device__ __forceinline__ void cp_async16(uint32_t dst, const void* src) {
    asm volatile("cp.async.cg.shared.global [%0], [%1], 16;"
                 :: "r"(dst), "l"(src) : "memory");
}
#define CP_COMMIT() asm volatile("cp.async.commit_group;" ::: "memory")
#define CP_WAIT(n)  asm volatile("cp.async.wait_group %0;" :: "n"(n) : "memory")

__device__ __forceinline__ void ldmatrix_x4(uint32_t& r0, uint32_t& r1,
                                            uint32_t& r2, uint32_t& r3, uint32_t addr) {
    asm volatile("ldmatrix.sync.aligned.m8n8.x4.shared.b16 {%0,%1,%2,%3}, [%4];"
                 : "=r"(r0), "=r"(r1), "=r"(r2), "=r"(r3) : "r"(addr));
}
__device__ __forceinline__ void mma_bf16(float* d, const uint32_t* a, const uint32_t* b) {
    asm volatile(
        "mma.sync.aligned.m16n8k16.row.col.f32.bf16.bf16.f32 "
        "{%0,%1,%2,%3}, {%4,%5,%6,%7}, {%8,%9}, {%0,%1,%2,%3};"
        : "+f"(d[0]), "+f"(d[1]), "+f"(d[2]), "+f"(d[3])
        : "r"(a[0]), "r"(a[1]), "r"(a[2]), "r"(a[3]), "r"(b[0]), "r"(b[1]));
}

// ================= split-bf16 tensor-core GEMM (HMMA path) =================
// C[M,N] = (Ah+Al)[M,K] @ (Bh+Bl)[N,K]^T (+bias)(+res)(relu); batched over z.
// CTA tile 128 x BN, BK=32. 8 warps in 4(M) x 2(N). Warp tile 32 x BN/2.
// SMEM rows are 64B (32 bf16) with XOR-16B-group swizzle: grp ^= (row>>1)&3.
template<int BN, bool BIAS, bool RELU, bool RES>
__global__ __launch_bounds__(256, 1) void mma_gemm(
    const __nv_bfloat16* __restrict__ Ah, const __nv_bfloat16* __restrict__ Al,
    const __nv_bfloat16* __restrict__ Bh, const __nv_bfloat16* __restrict__ Bl,
    const float* __restrict__ bias, const float* __restrict__ res,
    float* __restrict__ C, int M, int N, int K,
    long long zA, long long zB, long long zC)
{
    constexpr int BM = 128, BK = 32;
    constexpr int NFRAG = BN / 16;          // n8-fragments per warp
    constexpr int ASZ = BM * 64;            // bytes per A matrix per stage (8192)
    constexpr int BSZ = BN * 64;
    constexpr int STAGE = 2 * ASZ + 2 * BSZ;

    extern __shared__ char smem[];
    const uint32_t sb = smem_to_u32(smem);

    const long long z = blockIdx.z;
    Ah += z * zA; Al += z * zA;
    Bh += z * zB; Bl += z * zB;
    C  += z * zC;
    const float* R = RES ? (res + z * zC) : nullptr;

    const int m0 = blockIdx.y * BM;
    const int n0 = blockIdx.x * BN;
    const int tid = threadIdx.x;
    const int lane = tid & 31;
    const int wid = tid >> 5;
    const int wm = wid >> 1;                // 0..3
    const int wn = wid & 1;                 // 0..1

    // ---- async loader for one K-chunk into stage s ----
    auto load_stage = [&](int kc, int s) {
        const uint32_t st = sb + s * STAGE;
        const int koff = kc * BK;
#pragma unroll
        for (int i = 0; i < (BM * 4) / 256; i++) {
            const int idx = tid + i * 256;
            const int row = idx >> 2, g = idx & 3;
            const uint32_t d = st + row * 64 + ((g ^ ((row >> 1) & 3)) << 4);
            const size_t src = (size_t)(m0 + row) * K + koff + g * 8;
            cp_async16(d,        Ah + src);
            cp_async16(d + ASZ,  Al + src);
        }
#pragma unroll
        for (int i = 0; i < (BN * 4) / 256; i++) {
            const int idx = tid + i * 256;
            const int row = idx >> 2, g = idx & 3;
            const uint32_t d = st + 2 * ASZ + row * 64 + ((g ^ ((row >> 1) & 3)) << 4);
            const size_t src = (size_t)(n0 + row) * K + koff + g * 8;
            cp_async16(d,        Bh + src);
            cp_async16(d + BSZ,  Bl + src);
        }
    };

    float acc[2][NFRAG][4];
#pragma unroll
    for (int mf = 0; mf < 2; mf++)
#pragma unroll
        for (int nf = 0; nf < NFRAG; nf++)
#pragma unroll
            for (int c = 0; c < 4; c++) acc[mf][nf][c] = 0.f;

    const int KC = K / BK;
    load_stage(0, 0);
    CP_COMMIT();

    for (int kc = 0; kc < KC; kc++) {
        if (kc + 1 < KC) {
            load_stage(kc + 1, (kc + 1) & 1);
            CP_COMMIT();
            CP_WAIT(1);
        } else {
            CP_WAIT(0);
        }
        __syncthreads();

        const uint32_t st = sb + (kc & 1) * STAGE;
#pragma unroll
        for (int ks = 0; ks < 2; ks++) {
            uint32_t afh[2][4], afl[2][4];
#pragma unroll
            for (int mf = 0; mf < 2; mf++) {
                const int row = wm * 32 + mf * 16 + (lane & 15);
                const int g = (ks * 2 + (lane >> 4)) ^ ((row >> 1) & 3);
                const uint32_t addr = st + row * 64 + (g << 4);
                ldmatrix_x4(afh[mf][0], afh[mf][1], afh[mf][2], afh[mf][3], addr);
                ldmatrix_x4(afl[mf][0], afl[mf][1], afl[mf][2], afl[mf][3], addr + ASZ);
            }
            uint32_t bfh[NFRAG][2], bfl[NFRAG][2];
#pragma unroll
            for (int nq = 0; nq < NFRAG / 2; nq++) {
                const int row = wn * (BN / 2) + nq * 16 + (lane & 15);
                const int g = (ks * 2 + (lane >> 4)) ^ ((row >> 1) & 3);
                const uint32_t addr = st + 2 * ASZ + row * 64 + (g << 4);
                uint32_t r0, r1, r2, r3;
                ldmatrix_x4(r0, r1, r2, r3, addr);
                bfh[2 * nq][0] = r0; bfh[2 * nq][1] = r2;
                bfh[2 * nq + 1][0] = r1; bfh[2 * nq + 1][1] = r3;
                ldmatrix_x4(r0, r1, r2, r3, addr + BSZ);
                bfl[2 * nq][0] = r0; bfl[2 * nq][1] = r2;
                bfl[2 * nq + 1][0] = r1; bfl[2 * nq + 1][1] = r3;
            }
#pragma unroll
            for (int mf = 0; mf < 2; mf++)
#pragma unroll
                for (int nf = 0; nf < NFRAG; nf++) {
                    mma_bf16(acc[mf][nf], afh[mf], bfh[nf]);   // hi*hi
                    mma_bf16(acc[mf][nf], afh[mf], bfl[nf]);   // hi*lo
                    mma_bf16(acc[mf][nf], afl[mf], bfh[nf]);   // lo*hi
                }
        }
        __syncthreads();
    }

    // ---- epilogue: direct float2 stores with fused bias/res/relu ----
#pragma unroll
    for (int mf = 0; mf < 2; mf++) {
        const int r0i = m0 + wm * 32 + mf * 16 + (lane >> 2);
#pragma unroll
        for (int nf = 0; nf < NFRAG; nf++) {
            const int col = n0 + wn * (BN / 2) + nf * 8 + (lane & 3) * 2;
            float2 bv = make_float2(0.f, 0.f);
            if (BIAS) { bv.x = bias[col]; bv.y = bias[col + 1]; }
#pragma unroll
            for (int hrow = 0; hrow < 2; hrow++) {
                const int rr = r0i + hrow * 8;
                float2 v;
                v.x = acc[mf][nf][2 * hrow + 0] + bv.x;
                v.y = acc[mf][nf][2 * hrow + 1] + bv.y;
                if (RES) {
                    const float2 rv = *(const float2*)(R + (size_t)rr * N + col);
                    v.x += rv.x; v.y += rv.y;
                }
                if (RELU) { v.x = fmaxf(v.x, 0.f); v.y = fmaxf(v.y, 0.f); }
                *(float2*)(C + (size_t)rr * N + col) = v;
            }
        }
    }
}

// ================= conversion kernels =================
__global__ __launch_bounds__(256) void split_kernel(
    const float* __restrict__ x, __nv_bfloat16* __restrict__ hi,
    __nv_bfloat16* __restrict__ lo, int n)
{
    const int i = (blockIdx.x * 256 + threadIdx.x) * 4;
    if (i >= n) return;
    const float4 v = *(const float4*)(x + i);
    __nv_bfloat16 h0 = __float2bfloat16(v.x);
    __nv_bfloat16 h1 = __float2bfloat16(v.y);
    __nv_bfloat16 h2 = __float2bfloat16(v.z);
    __nv_bfloat16 h3 = __float2bfloat16(v.w);
    __nv_bfloat16 l0 = __float2bfloat16(v.x - __bfloat162float(h0));
    __nv_bfloat16 l1 = __float2bfloat16(v.y - __bfloat162float(h1));
    __nv_bfloat16 l2 = __float2bfloat16(v.z - __bfloat162float(h2));
    __nv_bfloat16 l3 = __float2bfloat16(v.w - __bfloat162float(h3));
    __nv_bfloat162* ph = (__nv_bfloat162*)(hi + i);
    __nv_bfloat162* pl = (__nv_bfloat162*)(lo + i);
    ph[0] = __nv_bfloat162(h0, h1); ph[1] = __nv_bfloat162(h2, h3);
    pl[0] = __nv_bfloat162(l0, l1); pl[1] = __nv_bfloat162(l2, l3);
}

// fp32 W[R,C] -> bf16 split transpose Th/Tl[C,R]; batched over z with strides
__global__ __launch_bounds__(256) void trsplit_kernel(
    const float* __restrict__ W, __nv_bfloat16* __restrict__ Th,
    __nv_bfloat16* __restrict__ Tl, int R, int C, long long sIn, long long sOut)
{
    __shared__ float t[32][33];
    const int z = blockIdx.z;
    W  += (long long)z * sIn;
    Th += (long long)z * sOut;
    Tl += (long long)z * sOut;
    const int r0 = blockIdx.y * 32, c0 = blockIdx.x * 32;
    const int tx = threadIdx.x & 31, ty = threadIdx.x >> 5;   // 32 x 8
#pragma unroll
    for (int i = 0; i < 32; i += 8)
        t[ty + i][tx] = W[(long long)(r0 + ty + i) * C + c0 + tx];
    __syncthreads();
#pragma unroll
    for (int i = 0; i < 32; i += 8) {
        const float v = t[tx][ty + i];
        const __nv_bfloat16 h = __float2bfloat16(v);
        const __nv_bfloat16 l = __float2bfloat16(v - __bfloat162float(h));
        const long long o = (long long)(c0 + ty + i) * R + r0 + tx;
        Th[o] = h; Tl[o] = l;
    }
}

// qkv_all[T,3072] -> q/k/v [H][B*S][64]
__global__ __launch_bounds__(256) void qkv_reorder(
    const float* __restrict__ qa, float* __restrict__ q,
    float* __restrict__ k, float* __restrict__ v)
{
    const int idx = blockIdx.x * 256 + threadIdx.x;
    const int kd = idx & 63;
    const int t  = (idx >> 6) & (MTOK - 1);
    const int h  = idx >> 18;
    const size_t src = (size_t)t * 3072 + h * 64 + kd;
    q[idx] = qa[src];
    k[idx] = qa[src + 1024];
    v[idx] = qa[src + 2048];
}

// ================= LayerNorm =================
__global__ __launch_bounds__(256) void ln_kernel(
    const float* __restrict__ x, const float* __restrict__ g,
    const float* __restrict__ b, float* __restrict__ out)
{
    __shared__ float row[EE];
    __shared__ float red[256];
    const int r = blockIdx.x;
    const int t = threadIdx.x;
    const float* xr = x + (size_t)r * EE;

    float s = 0.f;
    for (int i = t; i < EE; i += 256) { float v = xr[i]; row[i] = v; s += v; }
    red[t] = s; __syncthreads();
    for (int o = 128; o > 0; o >>= 1) { if (t < o) red[t] += red[t + o]; __syncthreads(); }
    const float mean = red[0] * (1.0f / EE);
    __syncthreads();

    float vs = 0.f;
    for (int i = t; i < EE; i += 256) { float d = row[i] - mean; vs += d * d; }
    red[t] = vs; __syncthreads();
    for (int o = 128; o > 0; o >>= 1) { if (t < o) red[t] += red[t + o]; __syncthreads(); }
    const float rstd = rsqrtf(red[0] * (1.0f / EE) + LNEPS);

    float* orow = out + (size_t)r * EE;
    for (int i = t; i < EE; i += 256)
        orow[i] = (row[i] - mean) * rstd * g[i] + b[i];
}

// ================= causal softmax (scale + faithful mask) =================
__global__ __launch_bounds__(256) void softmax_kernel(float* __restrict__ sc)
{
    __shared__ float row[SS];
    __shared__ float red[256];
    const long long r = blockIdx.x;
    const int i = (int)(r % SS);
    const int n = i + 1;
    float* p = sc + r * (long long)SS;
    const int t = threadIdx.x;
    const float scale = 0.125f;

    float m = -INFINITY;
    for (int j = t; j < n; j += 256) {
        float raw = p[j];
        float s = (raw == 0.f) ? -INFINITY : raw * scale;
        row[j] = s;
        m = fmaxf(m, s);
    }
    red[t] = m; __syncthreads();
    for (int o = 128; o > 0; o >>= 1) { if (t < o) red[t] = fmaxf(red[t], red[t + o]); __syncthreads(); }
    m = red[0]; __syncthreads();

    float ssum = 0.f;
    for (int j = t; j < n; j += 256) {
        float e = __expf(row[j] - m);
        row[j] = e;
        ssum += e;
    }
    red[t] = ssum; __syncthreads();
    for (int o = 128; o > 0; o >>= 1) { if (t < o) red[t] += red[t + o]; __syncthreads(); }
    const float inv = 1.f / red[0];

    for (int j = t; j < n; j += 256) p[j] = row[j] * inv;
    for (int j = t; j < SS; j += 256) if (j >= n) p[j] = 0.f;
}

// ================= head-major -> concat reorder =================
__global__ __launch_bounds__(256) void reorder_kernel(
    const float* __restrict__ in, float* __restrict__ out)
{
    int idx = blockIdx.x * 256 + threadIdx.x;
    int vd = idx % VDIM;
    int rest = idx / VDIM;
    int s = rest % SS; rest /= SS;
    int b = rest % BB;
    int h = rest / BB;
    out[((size_t)(b * SS + s)) * EE + h * VDIM + vd] = in[idx];
}

// ================= launcher =================
extern "C" void kernel_launch(void* const* d_in, const int* in_sizes, int n_in,
                              void* d_out, int out_size)
{
    (void)in_sizes; (void)n_in; (void)out_size;
    const float* x      = (const float*)d_in[0];
    const float* ln1_g  = (const float*)d_in[1];
    const float* ln1_b  = (const float*)d_in[2];
    const float* Wq     = (const float*)d_in[3];
    const float* Wk     = (const float*)d_in[4];
    const float* Wv     = (const float*)d_in[5];
    const float* proj_W = (const float*)d_in[6];
    const float* proj_b = (const float*)d_in[7];
    const float* ln2_g  = (const float*)d_in[8];
    const float* ln2_b  = (const float*)d_in[9];
    const float* fin_W  = (const float*)d_in[10];
    const float* fin_b  = (const float*)d_in[11];
    const float* hid_W  = (const float*)d_in[12];
    const float* hid_b  = (const float*)d_in[13];
    const float* fout_W = (const float*)d_in[14];
    const float* fout_b = (const float*)d_in[15];
    float* out = (float*)d_out;

    float *h, *q, *k, *v, *sc, *ot, *oc, *x1, *f1, *f2;
    __nv_bfloat16 *ah, *al, *bh, *bl, *qh, *ql, *kh, *kl, *vth, *vtl, *ph, *pl;
    cudaGetSymbolAddress((void**)&h,  g_h);
    cudaGetSymbolAddress((void**)&q,  g_q);
    cudaGetSymbolAddress((void**)&k,  g_k);
    cudaGetSymbolAddress((void**)&v,  g_v);
    cudaGetSymbolAddress((void**)&sc, g_sc);
    cudaGetSymbolAddress((void**)&ot, g_ot);
    cudaGetSymbolAddress((void**)&oc, g_oc);
    cudaGetSymbolAddress((void**)&x1, g_x1);
    cudaGetSymbolAddress((void**)&f1, g_f1);
    cudaGetSymbolAddress((void**)&f2, g_f2);
    cudaGetSymbolAddress((void**)&ah, g_ah);
    cudaGetSymbolAddress((void**)&al, g_al);
    cudaGetSymbolAddress((void**)&bh, g_bh);
    cudaGetSymbolAddress((void**)&bl, g_bl);
    cudaGetSymbolAddress((void**)&qh, g_qh);
    cudaGetSymbolAddress((void**)&ql, g_ql);
    cudaGetSymbolAddress((void**)&kh, g_kh);
    cudaGetSymbolAddress((void**)&kl, g_kl);
    cudaGetSymbolAddress((void**)&vth, g_vth);
    cudaGetSymbolAddress((void**)&vtl, g_vtl);
    cudaGetSymbolAddress((void**)&ph, g_ph);
    cudaGetSymbolAddress((void**)&pl, g_pl);

    // dynamic smem opt-in
    constexpr int SM128 = 2 * (2 * 128 * 64 + 2 * 128 * 64);   // 65536
    constexpr int SM64  = 2 * (2 * 128 * 64 + 2 * 64 * 64);    // 49152
    cudaFuncSetAttribute((const void*)mma_gemm<128, false, false, false>,
                         cudaFuncAttributeMaxDynamicSharedMemorySize, SM128);
    cudaFuncSetAttribute((const void*)mma_gemm<128, true, false, true>,
                         cudaFuncAttributeMaxDynamicSharedMemorySize, SM128);
    cudaFuncSetAttribute((const void*)mma_gemm<128, true, true, false>,
                         cudaFuncAttributeMaxDynamicSharedMemorySize, SM128);
    cudaFuncSetAttribute((const void*)mma_gemm<64, false, false, false>,
                         cudaFuncAttributeMaxDynamicSharedMemorySize, SM64);

    // ---------- attention ----------
    ln_kernel<<<MTOK, 256>>>(x, ln1_g, ln1_b, h);

    // QKV as one GEMM: [4096,1024] @ [3072,1024]^T
    split_kernel<<<MTOK * EE / 1024, 256>>>(h, ah, al, MTOK * EE);
    {
        dim3 g(KDIM / 32, EE / 32, HH);
        trsplit_kernel<<<g, 256>>>(Wq, bh, bl, EE, KDIM,
                                   (long long)EE * KDIM, (long long)KDIM * EE);
        trsplit_kernel<<<g, 256>>>(Wk, bh + (size_t)1024 * EE, bl + (size_t)1024 * EE,
                                   EE, KDIM, (long long)EE * KDIM, (long long)KDIM * EE);
        trsplit_kernel<<<g, 256>>>(Wv, bh + (size_t)2048 * EE, bl + (size_t)2048 * EE,
                                   EE, KDIM, (long long)EE * KDIM, (long long)KDIM * EE);
    }
    mma_gemm<128, false, false, false><<<dim3(3072 / 128, MTOK / 128, 1), 256, SM128>>>(
        ah, al, bh, bl, nullptr, nullptr, f1, MTOK, 3072, EE, 0LL, 0LL, 0LL);
    qkv_reorder<<<HH * MTOK * KDIM / 256, 256>>>(f1, q, k, v);

    // scores = q @ k^T (batched z=64, K=64)
    split_kernel<<<HH * MTOK * KDIM / 1024, 256>>>(q, qh, ql, HH * MTOK * KDIM);
    split_kernel<<<HH * MTOK * KDIM / 1024, 256>>>(k, kh, kl, HH * MTOK * KDIM);
    mma_gemm<128, false, false, false><<<dim3(SS / 128, SS / 128, HH * BB), 256, SM128>>>(
        qh, ql, kh, kl, nullptr, nullptr, sc, SS, SS, KDIM,
        (long long)SS * KDIM, (long long)SS * KDIM, (long long)SS * SS);

    softmax_kernel<<<HH * BB * SS, 256>>>(sc);

    // O = P @ V  (B operand is V^T [64, S] per batch)
    split_kernel<<<(int)(((size_t)HH * BB * SS * SS) / 1024), 256>>>(
        sc, ph, pl, (int)((size_t)HH * BB * SS * SS));
    trsplit_kernel<<<dim3(VDIM / 32, SS / 32, HH * BB), 256>>>(
        v, vth, vtl, SS, VDIM, (long long)SS * VDIM, (long long)VDIM * SS);
    mma_gemm<64, false, false, false><<<dim3(VDIM / 64, SS / 128, HH * BB), 256, SM64>>>(
        ph, pl, vth, vtl, nullptr, nullptr, ot, SS, VDIM, SS,
        (long long)SS * SS, (long long)VDIM * SS, (long long)SS * VDIM);

    reorder_kernel<<<(HH * MTOK * VDIM) / 256, 256>>>(ot, oc);

    // x1 = x + oc @ proj_W + proj_b
    split_kernel<<<MTOK * EE / 1024, 256>>>(oc, ah, al, MTOK * EE);
    trsplit_kernel<<<dim3(EE / 32, EE / 32, 1), 256>>>(proj_W, bh, bl, EE, EE, 0LL, 0LL);
    mma_gemm<128, true, false, true><<<dim3(EE / 128, MTOK / 128, 1), 256, SM128>>>(
        ah, al, bh, bl, proj_b, x, x1, MTOK, EE, EE, 0LL, 0LL, 0LL);

    // ---------- FFN ----------
    ln_kernel<<<MTOK, 256>>>(x1, ln2_g, ln2_b, h);

    split_kernel<<<MTOK * EE / 1024, 256>>>(h, ah, al, MTOK * EE);
    trsplit_kernel<<<dim3(DD / 32, EE / 32, 1), 256>>>(fin_W, bh, bl, EE, DD, 0LL, 0LL);
    mma_gemm<128, true, true, false><<<dim3(DD / 128, MTOK / 128, 1), 256, SM128>>>(
        ah, al, bh, bl, fin_b, nullptr, f1, MTOK, DD, EE, 0LL, 0LL, 0LL);

    split_kernel<<<(int)((size_t)MTOK * DD / 1024), 256>>>(f1, ah, al, MTOK * DD);
    trsplit_kernel<<<dim3(DD / 32, DD / 32, 1), 256>>>(hid_W, bh, bl, DD, DD, 0LL, 0LL);
    mma_gemm<128, true, true, false><<<dim3(DD / 128, MTOK / 128, 1), 256, SM128>>>(
        ah, al, bh, bl, hid_b, nullptr, f2, MTOK, DD, DD, 0LL, 0LL, 0LL);

    split_kernel<<<(int)((size_t)MTOK * DD / 1024), 256>>>(f2, ah, al, MTOK * DD);
    trsplit_kernel<<<dim3(DD / 32, DD / 32, 1), 256>>>(
        hid_W + (size_t)DD * DD, bh, bl, DD, DD, 0LL, 0LL);
    mma_gemm<128, true, true, false><<<dim3(DD / 128, MTOK / 128, 1), 256, SM128>>>(
        ah, al, bh, bl, hid_b + DD, nullptr, f1, MTOK, DD, DD, 0LL, 0LL, 0LL);

    split_kernel<<<(int)((size_t)MTOK * DD / 1024), 256>>>(f1, ah, al, MTOK * DD);
    trsplit_kernel<<<dim3(EE / 32, DD / 32, 1), 256>>>(fout_W, bh, bl, DD, EE, 0LL, 0LL);
    mma_gemm<128, true, false, true><<<dim3(EE / 128, MTOK / 128, 1), 256, SM128>>>(
        ah, al, bh, bl, fout_b, x1, out, MTOK, EE, DD, 0LL, 0LL, 0LL);
}

// round 7
// speedup vs baseline: 2.8947x; 1.1071x over previous
#include <cuda_runtime.h>
#include <cuda_bf16.h>
#include <math.h>
#include <stdint.h>
#include <string.h>

// ---------------- problem constants ----------------
#define BB   4
#define SS   1024
#define EE   1024
#define HH   16
#define KDIM 64
#define VDIM 64
#define DD   4096
#define MTOK 4096            // B*S tokens
#define LNEPS 1e-5f

// ---------------- device scratch (static globals; no allocations) ----------------
__device__ float g_h [MTOK * EE];
__device__ float g_x1[MTOK * EE];
__device__ __nv_bfloat16 g_sah[(size_t)MTOK * DD];
__device__ __nv_bfloat16 g_sal[(size_t)MTOK * DD];
__device__ __nv_bfloat16 g_sbh[(size_t)MTOK * DD];
__device__ __nv_bfloat16 g_sbl[(size_t)MTOK * DD];
__device__ __nv_bfloat16 g_wh[(size_t)DD * DD];
__device__ __nv_bfloat16 g_wl[(size_t)DD * DD];
__device__ __nv_bfloat16 g_qh[HH * MTOK * KDIM];
__device__ __nv_bfloat16 g_ql[HH * MTOK * KDIM];
__device__ __nv_bfloat16 g_kh[HH * MTOK * KDIM];
__device__ __nv_bfloat16 g_kl[HH * MTOK * KDIM];
__device__ __nv_bfloat16 g_vh[HH * MTOK * VDIM];
__device__ __nv_bfloat16 g_vl[HH * MTOK * VDIM];

// ================= low-level helpers (sm_80+ base-target PTX only) =================
__device__ __forceinline__ uint32_t smem_to_u32(const void* p) {
    uint32_t a;
    asm("{ .reg .u64 t; cvta.to.shared.u64 t, %1; cvt.u32.u64 %0, t; }"
        : "=r"(a) : "l"(p));
    return a;
}
__device__ __forceinline__ void cp_async16(uint32_t dst, const void* src) {
    asm volatile("cp.async.cg.shared.global [%0], [%1], 16;"
                 :: "r"(dst), "l"(src) : "memory");
}
#define CP_COMMIT() asm volatile("cp.async.commit_group;" ::: "memory")
#define CP_WAIT(n)  asm volatile("cp.async.wait_group %0;" :: "n"(n) : "memory")

__device__ __forceinline__ void ldmatrix_x4(uint32_t& r0, uint32_t& r1,
                                            uint32_t& r2, uint32_t& r3, uint32_t addr) {
    asm volatile("ldmatrix.sync.aligned.m8n8.x4.shared.b16 {%0,%1,%2,%3}, [%4];"
                 : "=r"(r0), "=r"(r1), "=r"(r2), "=r"(r3) : "r"(addr));
}
__device__ __forceinline__ void ldmatrix_x4_trans(uint32_t& r0, uint32_t& r1,
                                                  uint32_t& r2, uint32_t& r3, uint32_t addr) {
    asm volatile("ldmatrix.sync.aligned.m8n8.x4.trans.shared.b16 {%0,%1,%2,%3}, [%4];"
                 : "=r"(r0), "=r"(r1), "=r"(r2), "=r"(r3) : "r"(addr));
}
__device__ __forceinline__ void mma_bf16(float* d, const uint32_t* a, const uint32_t* b) {
    asm volatile(
        "mma.sync.aligned.m16n8k16.row.col.f32.bf16.bf16.f32 "
        "{%0,%1,%2,%3}, {%4,%5,%6,%7}, {%8,%9}, {%0,%1,%2,%3};"
        : "+f"(d[0]), "+f"(d[1]), "+f"(d[2]), "+f"(d[3])
        : "r"(a[0]), "r"(a[1]), "r"(a[2]), "r"(a[3]), "r"(b[0]), "r"(b[1]));
}
__device__ __forceinline__ uint32_t pack_bf16x2(__nv_bfloat16 a, __nv_bfloat16 b) {
    return (uint32_t)__bfloat16_as_ushort(a) | ((uint32_t)__bfloat16_as_ushort(b) << 16);
}

// ================= split-bf16 tensor-core GEMM (HMMA path) =================
// C[M,N] = (Ah+Al)[M,K] @ (Bh+Bl)[N,K]^T (+bias)(+res)(relu).
// OSPLIT: write result as bf16 hi/lo pair instead of fp32.
// CTA tile 128 x 128, BK=32. 8 warps in 4(M) x 2(N). Warp tile 32 x 64.
template<bool BIAS, bool RELU, bool RES, bool OSPLIT>
__global__ __launch_bounds__(256, 1) void mma_gemm(
    const __nv_bfloat16* __restrict__ Ah, const __nv_bfloat16* __restrict__ Al,
    const __nv_bfloat16* __restrict__ Bh, const __nv_bfloat16* __restrict__ Bl,
    const float* __restrict__ bias, const float* __restrict__ res,
    float* __restrict__ C, __nv_bfloat16* __restrict__ Ch,
    __nv_bfloat16* __restrict__ Cl, int M, int N, int K)
{
    constexpr int BM = 128, BN = 128, BK = 32;
    constexpr int NFRAG = BN / 16;          // 8
    constexpr int ASZ = BM * 64;            // 8192 bytes per matrix per stage
    constexpr int BSZ = BN * 64;
    constexpr int STAGE = 2 * ASZ + 2 * BSZ;

    extern __shared__ char smem[];
    const uint32_t sb = smem_to_u32(smem);

    const int m0 = blockIdx.y * BM;
    const int n0 = blockIdx.x * BN;
    const int tid = threadIdx.x;
    const int lane = tid & 31;
    const int wid = tid >> 5;
    const int wm = wid >> 1;
    const int wn = wid & 1;

    auto load_stage = [&](int kc, int s) {
        const uint32_t st = sb + s * STAGE;
        const int koff = kc * BK;
#pragma unroll
        for (int i = 0; i < (BM * 4) / 256; i++) {
            const int idx = tid + i * 256;
            const int row = idx >> 2, g = idx & 3;
            const uint32_t d = st + row * 64 + ((g ^ ((row >> 1) & 3)) << 4);
            const size_t src = (size_t)(m0 + row) * K + koff + g * 8;
            cp_async16(d,        Ah + src);
            cp_async16(d + ASZ,  Al + src);
        }
#pragma unroll
        for (int i = 0; i < (BN * 4) / 256; i++) {
            const int idx = tid + i * 256;
            const int row = idx >> 2, g = idx & 3;
            const uint32_t d = st + 2 * ASZ + row * 64 + ((g ^ ((row >> 1) & 3)) << 4);
            const size_t src = (size_t)(n0 + row) * K + koff + g * 8;
            cp_async16(d,        Bh + src);
            cp_async16(d + BSZ,  Bl + src);
        }
    };

    float acc[2][NFRAG][4];
#pragma unroll
    for (int i = 0; i < 2; i++)
#pragma unroll
        for (int j = 0; j < NFRAG; j++)
#pragma unroll
            for (int c = 0; c < 4; c++) acc[i][j][c] = 0.f;

    const int KC = K / BK;
    load_stage(0, 0);
    CP_COMMIT();

    for (int kc = 0; kc < KC; kc++) {
        if (kc + 1 < KC) {
            load_stage(kc + 1, (kc + 1) & 1);
            CP_COMMIT();
            CP_WAIT(1);
        } else {
            CP_WAIT(0);
        }
        __syncthreads();

        const uint32_t st = sb + (kc & 1) * STAGE;
#pragma unroll
        for (int ks = 0; ks < 2; ks++) {
            uint32_t afh[2][4], afl[2][4];
#pragma unroll
            for (int mf = 0; mf < 2; mf++) {
                const int row = wm * 32 + mf * 16 + (lane & 15);
                const int g = (ks * 2 + (lane >> 4)) ^ ((row >> 1) & 3);
                const uint32_t addr = st + row * 64 + (g << 4);
                ldmatrix_x4(afh[mf][0], afh[mf][1], afh[mf][2], afh[mf][3], addr);
                ldmatrix_x4(afl[mf][0], afl[mf][1], afl[mf][2], afl[mf][3], addr + ASZ);
            }
            uint32_t bfh[NFRAG][2], bfl[NFRAG][2];
#pragma unroll
            for (int nq = 0; nq < NFRAG / 2; nq++) {
                const int row = wn * (BN / 2) + nq * 16 + (lane & 15);
                const int g = (ks * 2 + (lane >> 4)) ^ ((row >> 1) & 3);
                const uint32_t addr = st + 2 * ASZ + row * 64 + (g << 4);
                uint32_t r0, r1, r2, r3;
                ldmatrix_x4(r0, r1, r2, r3, addr);
                bfh[2 * nq][0] = r0; bfh[2 * nq][1] = r2;
                bfh[2 * nq + 1][0] = r1; bfh[2 * nq + 1][1] = r3;
                ldmatrix_x4(r0, r1, r2, r3, addr + BSZ);
                bfl[2 * nq][0] = r0; bfl[2 * nq][1] = r2;
                bfl[2 * nq + 1][0] = r1; bfl[2 * nq + 1][1] = r3;
            }
#pragma unroll
            for (int mf = 0; mf < 2; mf++)
#pragma unroll
                for (int nf = 0; nf < NFRAG; nf++) {
                    mma_bf16(acc[mf][nf], afh[mf], bfh[nf]);
                    mma_bf16(acc[mf][nf], afh[mf], bfl[nf]);
                    mma_bf16(acc[mf][nf], afl[mf], bfh[nf]);
                }
        }
        __syncthreads();
    }

    // ---- epilogue ----
#pragma unroll
    for (int mf = 0; mf < 2; mf++) {
        const int r0i = m0 + wm * 32 + mf * 16 + (lane >> 2);
#pragma unroll
        for (int nf = 0; nf < NFRAG; nf++) {
            const int col = n0 + wn * (BN / 2) + nf * 8 + (lane & 3) * 2;
            float2 bv = make_float2(0.f, 0.f);
            if (BIAS) { bv.x = bias[col]; bv.y = bias[col + 1]; }
#pragma unroll
            for (int hrow = 0; hrow < 2; hrow++) {
                const int rr = r0i + hrow * 8;
                float2 v;
                v.x = acc[mf][nf][2 * hrow + 0] + bv.x;
                v.y = acc[mf][nf][2 * hrow + 1] + bv.y;
                if (RES) {
                    const float2 rv = *(const float2*)(res + (size_t)rr * N + col);
                    v.x += rv.x; v.y += rv.y;
                }
                if (RELU) { v.x = fmaxf(v.x, 0.f); v.y = fmaxf(v.y, 0.f); }
                if (OSPLIT) {
                    const __nv_bfloat16 h0 = __float2bfloat16(v.x);
                    const __nv_bfloat16 h1 = __float2bfloat16(v.y);
                    const __nv_bfloat16 l0 = __float2bfloat16(v.x - __bfloat162float(h0));
                    const __nv_bfloat16 l1 = __float2bfloat16(v.y - __bfloat162float(h1));
                    *(uint32_t*)(Ch + (size_t)rr * N + col) = pack_bf16x2(h0, h1);
                    *(uint32_t*)(Cl + (size_t)rr * N + col) = pack_bf16x2(l0, l1);
                } else {
                    *(float2*)(C + (size_t)rr * N + col) = v;
                }
            }
        }
    }
}

// ================= flash attention (causal, faithful ==0 mask) =================
// grid (qt=8, hb=64); block 256 = 8 warps, warp w owns rows [16w,16w+16).
// q/k/v split bf16 [hb][S][64]; output split bf16 in concat layout [token][EE].
__global__ __launch_bounds__(256, 1) void flash_kernel(
    const __nv_bfloat16* __restrict__ qh, const __nv_bfloat16* __restrict__ ql,
    const __nv_bfloat16* __restrict__ kh, const __nv_bfloat16* __restrict__ kl,
    const __nv_bfloat16* __restrict__ vh, const __nv_bfloat16* __restrict__ vl,
    __nv_bfloat16* __restrict__ oh, __nv_bfloat16* __restrict__ ol)
{
    extern __shared__ char smem[];
    const uint32_t sb = smem_to_u32(smem);
    const int qt = blockIdx.x;
    const int hb = blockIdx.y;
    const int tid = threadIdx.x, lane = tid & 31, w = tid >> 5;

    const size_t hbase = (size_t)hb * SS * 64;
    const __nv_bfloat16* Qh = qh + hbase + (size_t)qt * 128 * 64;
    const __nv_bfloat16* Ql = ql + hbase + (size_t)qt * 128 * 64;
    const __nv_bfloat16* Kh = kh + hbase;
    const __nv_bfloat16* Kl = kl + hbase;
    const __nv_bfloat16* Vh = vh + hbase;
    const __nv_bfloat16* Vl = vl + hbase;

    // SMEM: [0,16K) Qh, [16K,32K) Ql; stage s at 32768+s*65536: Kh|Kl|Vh|Vl 16K each
#pragma unroll
    for (int i = 0; i < 4; i++) {
        const int idx = tid + i * 256;
        const int row = idx >> 3, g = idx & 7;
        const uint32_t off = row * 128 + ((g ^ (row & 7)) << 4);
        const size_t src = (size_t)row * 64 + g * 8;
        cp_async16(sb + off,         Qh + src);
        cp_async16(sb + 16384 + off, Ql + src);
    }
    auto load_kv = [&](int jt, int s) {
        const uint32_t st = sb + 32768 + s * 65536;
        const size_t base = (size_t)jt * 128 * 64;
#pragma unroll
        for (int i = 0; i < 4; i++) {
            const int idx = tid + i * 256;
            const int row = idx >> 3, g = idx & 7;
            const uint32_t off = row * 128 + ((g ^ (row & 7)) << 4);
            const size_t src = base + (size_t)row * 64 + g * 8;
            cp_async16(st + off,         Kh + src);
            cp_async16(st + 16384 + off, Kl + src);
            cp_async16(st + 32768 + off, Vh + src);
            cp_async16(st + 49152 + off, Vl + src);
        }
    };
    load_kv(0, 0);
    CP_COMMIT();

    uint32_t qfh[4][4], qfl[4][4];
    float ofr[8][4];
    float mrow[2] = {-INFINITY, -INFINITY};
    float lrow[2] = {0.f, 0.f};
#pragma unroll
    for (int f = 0; f < 8; f++)
#pragma unroll
        for (int c = 0; c < 4; c++) ofr[f][c] = 0.f;

    const int rb = qt * 128 + w * 16 + (lane >> 2);

    for (int jt = 0; jt <= qt; jt++) {
        if (jt < qt) { load_kv(jt + 1, (jt + 1) & 1); CP_COMMIT(); CP_WAIT(1); }
        else CP_WAIT(0);
        __syncthreads();

        if (jt == 0) {
#pragma unroll
            for (int kk = 0; kk < 4; kk++) {
                const int row = w * 16 + (lane & 15);
                const uint32_t c = (uint32_t)((kk * 2 + (lane >> 4)) ^ (row & 7));
                const uint32_t addr = sb + row * 128 + (c << 4);
                ldmatrix_x4(qfh[kk][0], qfh[kk][1], qfh[kk][2], qfh[kk][3], addr);
                ldmatrix_x4(qfl[kk][0], qfl[kk][1], qfl[kk][2], qfl[kk][3], addr + 16384);
            }
        }

        const uint32_t st = sb + 32768 + (jt & 1) * 65536;

        // ---- S = Q K^T (split: hh + hl + lh) ----
        float cfr[16][4];
#pragma unroll
        for (int f = 0; f < 16; f++)
#pragma unroll
            for (int c = 0; c < 4; c++) cfr[f][c] = 0.f;

#pragma unroll
        for (int kk = 0; kk < 4; kk++) {
#pragma unroll
            for (int nq = 0; nq < 8; nq++) {
                const int row = nq * 16 + (lane & 15);
                const uint32_t c = (uint32_t)((kk * 2 + (lane >> 4)) ^ (row & 7));
                const uint32_t addr = st + row * 128 + (c << 4);
                uint32_t r0, r1, r2, r3, s0, s1, s2, s3;
                ldmatrix_x4(r0, r1, r2, r3, addr);
                ldmatrix_x4(s0, s1, s2, s3, addr + 16384);
                uint32_t bh0[2] = {r0, r2}, bh1[2] = {r1, r3};
                uint32_t bl0[2] = {s0, s2}, bl1[2] = {s1, s3};
                mma_bf16(cfr[2 * nq],     qfh[kk], bh0);
                mma_bf16(cfr[2 * nq],     qfh[kk], bl0);
                mma_bf16(cfr[2 * nq],     qfl[kk], bh0);
                mma_bf16(cfr[2 * nq + 1], qfh[kk], bh1);
                mma_bf16(cfr[2 * nq + 1], qfh[kk], bl1);
                mma_bf16(cfr[2 * nq + 1], qfl[kk], bh1);
            }
        }

        // ---- mask + scale + row max ----
        float tm[2] = {-INFINITY, -INFINITY};
#pragma unroll
        for (int f = 0; f < 16; f++) {
            const int col = jt * 128 + f * 8 + (lane & 3) * 2;
#pragma unroll
            for (int h2 = 0; h2 < 2; h2++) {
                const int rg = rb + h2 * 8;
                float v0 = cfr[f][2 * h2], v1 = cfr[f][2 * h2 + 1];
                v0 = (v0 == 0.f || col > rg)     ? -INFINITY : v0 * 0.125f;
                v1 = (v1 == 0.f || col + 1 > rg) ? -INFINITY : v1 * 0.125f;
                cfr[f][2 * h2] = v0; cfr[f][2 * h2 + 1] = v1;
                tm[h2] = fmaxf(tm[h2], fmaxf(v0, v1));
            }
        }
#pragma unroll
        for (int h2 = 0; h2 < 2; h2++) {
            tm[h2] = fmaxf(tm[h2], __shfl_xor_sync(0xffffffffu, tm[h2], 1));
            tm[h2] = fmaxf(tm[h2], __shfl_xor_sync(0xffffffffu, tm[h2], 2));
            const float mn = fmaxf(mrow[h2], tm[h2]);
            const float alpha = __expf(mrow[h2] - mn);
            mrow[h2] = mn;
            lrow[h2] *= alpha;
#pragma unroll
            for (int f = 0; f < 8; f++) {
                ofr[f][2 * h2]     *= alpha;
                ofr[f][2 * h2 + 1] *= alpha;
            }
        }
        // ---- exponentiate + row sum ----
        float rs[2] = {0.f, 0.f};
#pragma unroll
        for (int f = 0; f < 16; f++) {
#pragma unroll
            for (int h2 = 0; h2 < 2; h2++) {
                const float p0 = __expf(cfr[f][2 * h2]     - mrow[h2]);
                const float p1 = __expf(cfr[f][2 * h2 + 1] - mrow[h2]);
                cfr[f][2 * h2] = p0; cfr[f][2 * h2 + 1] = p1;
                rs[h2] += p0 + p1;
            }
        }
#pragma unroll
        for (int h2 = 0; h2 < 2; h2++) {
            rs[h2] += __shfl_xor_sync(0xffffffffu, rs[h2], 1);
            rs[h2] += __shfl_xor_sync(0xffffffffu, rs[h2], 2);
            lrow[h2] += rs[h2];
        }

        // ---- O += P V (P split in registers; V split from SMEM via trans) ----
#pragma unroll
        for (int kk2 = 0; kk2 < 8; kk2++) {
            uint32_t pah[4], pal[4];
#pragma unroll
            for (int r = 0; r < 4; r++) {
                const int f = 2 * kk2 + (r >> 1);
                const int c0 = (r & 1) * 2;
                const float f0 = cfr[f][c0], f1 = cfr[f][c0 + 1];
                const __nv_bfloat16 h0 = __float2bfloat16(f0);
                const __nv_bfloat16 h1 = __float2bfloat16(f1);
                const __nv_bfloat16 l0 = __float2bfloat16(f0 - __bfloat162float(h0));
                const __nv_bfloat16 l1 = __float2bfloat16(f1 - __bfloat162float(h1));
                pah[r] = pack_bf16x2(h0, h1);
                pal[r] = pack_bf16x2(l0, l1);
            }
#pragma unroll
            for (int of2 = 0; of2 < 4; of2++) {
                const int row = kk2 * 16 + (lane & 15);
                const uint32_t c = (uint32_t)((of2 * 2 + (lane >> 4)) ^ (row & 7));
                const uint32_t addr = st + 32768 + row * 128 + (c << 4);
                uint32_t d0, d1, d2, d3, e0, e1, e2, e3;
                ldmatrix_x4_trans(d0, d1, d2, d3, addr);
                ldmatrix_x4_trans(e0, e1, e2, e3, addr + 16384);
                uint32_t v0h[2] = {d0, d1}, v1h[2] = {d2, d3};
                uint32_t v0l[2] = {e0, e1}, v1l[2] = {e2, e3};
                mma_bf16(ofr[2 * of2],     pah, v0h);
                mma_bf16(ofr[2 * of2],     pah, v0l);
                mma_bf16(ofr[2 * of2],     pal, v0h);
                mma_bf16(ofr[2 * of2 + 1], pah, v1h);
                mma_bf16(ofr[2 * of2 + 1], pah, v1l);
                mma_bf16(ofr[2 * of2 + 1], pal, v1h);
            }
        }
        __syncthreads();
    }

    // ---- finalize: O /= l, write split bf16 in concat layout ----
    const float inv0 = 1.f / lrow[0], inv1 = 1.f / lrow[1];
    const int hI = hb >> 2, bI = hb & 3;
    const int s0 = qt * 128 + w * 16 + (lane >> 2);
#pragma unroll
    for (int f = 0; f < 8; f++) {
        const int col = hI * 64 + f * 8 + (lane & 3) * 2;
#pragma unroll
        for (int h2 = 0; h2 < 2; h2++) {
            const int token = bI * SS + s0 + h2 * 8;
            const float inv = h2 ? inv1 : inv0;
            const float a = ofr[f][2 * h2] * inv;
            const float b = ofr[f][2 * h2 + 1] * inv;
            const __nv_bfloat16 h0 = __float2bfloat16(a);
            const __nv_bfloat16 h1 = __float2bfloat16(b);
            const __nv_bfloat16 l0 = __float2bfloat16(a - __bfloat162float(h0));
            const __nv_bfloat16 l1 = __float2bfloat16(b - __bfloat162float(h1));
            *(uint32_t*)(oh + (size_t)token * EE + col) = pack_bf16x2(h0, h1);
            *(uint32_t*)(ol + (size_t)token * EE + col) = pack_bf16x2(l0, l1);
        }
    }
}

// ================= conversion kernels =================
__global__ __launch_bounds__(256) void split_kernel(
    const float* __restrict__ x, __nv_bfloat16* __restrict__ hi,
    __nv_bfloat16* __restrict__ lo, int n)
{
    const int i = (blockIdx.x * 256 + threadIdx.x) * 4;
    if (i >= n) return;
    const float4 v = *(const float4*)(x + i);
    const __nv_bfloat16 h0 = __float2bfloat16(v.x);
    const __nv_bfloat16 h1 = __float2bfloat16(v.y);
    const __nv_bfloat16 h2 = __float2bfloat16(v.z);
    const __nv_bfloat16 h3 = __float2bfloat16(v.w);
    const __nv_bfloat16 l0 = __float2bfloat16(v.x - __bfloat162float(h0));
    const __nv_bfloat16 l1 = __float2bfloat16(v.y - __bfloat162float(h1));
    const __nv_bfloat16 l2 = __float2bfloat16(v.z - __bfloat162float(h2));
    const __nv_bfloat16 l3 = __float2bfloat16(v.w - __bfloat162float(h3));
    uint2* ph = (uint2*)(hi + i);
    uint2* pl = (uint2*)(lo + i);
    *ph = make_uint2(pack_bf16x2(h0, h1), pack_bf16x2(h2, h3));
    *pl = make_uint2(pack_bf16x2(l0, l1), pack_bf16x2(l2, l3));
}

// fp32 W[R,C] -> bf16 split transpose Th/Tl[C,R]; batched over z with strides
__global__ __launch_bounds__(256) void trsplit_kernel(
    const float* __restrict__ W, __nv_bfloat16* __restrict__ Th,
    __nv_bfloat16* __restrict__ Tl, int R, int C, long long sIn, long long sOut)
{
    __shared__ float t[32][33];
    const int z = blockIdx.z;
    W  += (long long)z * sIn;
    Th += (long long)z * sOut;
    Tl += (long long)z * sOut;
    const int r0 = blockIdx.y * 32, c0 = blockIdx.x * 32;
    const int tx = threadIdx.x & 31, ty = threadIdx.x >> 5;
#pragma unroll
    for (int i = 0; i < 32; i += 8)
        t[ty + i][tx] = W[(long long)(r0 + ty + i) * C + c0 + tx];
    __syncthreads();
#pragma unroll
    for (int i = 0; i < 32; i += 8) {
        const float v = t[tx][ty + i];
        const __nv_bfloat16 h = __float2bfloat16(v);
        const __nv_bfloat16 l = __float2bfloat16(v - __bfloat162float(h));
        const long long o = (long long)(c0 + ty + i) * R + r0 + tx;
        Th[o] = h; Tl[o] = l;
    }
}

// split QKV GEMM output [t][3072] -> q/k/v [hb][s][64] (hb = h*BB + b, t = b*SS + s)
__global__ __launch_bounds__(256) void qkv_reorder_bf(
    const __nv_bfloat16* __restrict__ sh, const __nv_bfloat16* __restrict__ sl,
    __nv_bfloat16* __restrict__ qh, __nv_bfloat16* __restrict__ ql,
    __nv_bfloat16* __restrict__ kh, __nv_bfloat16* __restrict__ kl,
    __nv_bfloat16* __restrict__ vh, __nv_bfloat16* __restrict__ vl)
{
    const int idx = blockIdx.x * 256 + threadIdx.x;
    const int kd = idx & 63;
    const int t  = (idx >> 6) & (MTOK - 1);
    const int h  = idx >> 18;
    const size_t src = (size_t)t * 3072 + h * 64 + kd;
    qh[idx] = sh[src];          ql[idx] = sl[src];
    kh[idx] = sh[src + 1024];   kl[idx] = sl[src + 1024];
    vh[idx] = sh[src + 2048];   vl[idx] = sl[src + 2048];
}

// ================= LayerNorm =================
__global__ __launch_bounds__(256) void ln_kernel(
    const float* __restrict__ x, const float* __restrict__ g,
    const float* __restrict__ b, float* __restrict__ out)
{
    __shared__ float row[EE];
    __shared__ float red[256];
    const int r = blockIdx.x;
    const int t = threadIdx.x;
    const float* xr = x + (size_t)r * EE;

    float s = 0.f;
    for (int i = t; i < EE; i += 256) { float v = xr[i]; row[i] = v; s += v; }
    red[t] = s; __syncthreads();
    for (int o = 128; o > 0; o >>= 1) { if (t < o) red[t] += red[t + o]; __syncthreads(); }
    const float mean = red[0] * (1.0f / EE);
    __syncthreads();

    float vs = 0.f;
    for (int i = t; i < EE; i += 256) { float d = row[i] - mean; vs += d * d; }
    red[t] = vs; __syncthreads();
    for (int o = 128; o > 0; o >>= 1) { if (t < o) red[t] += red[t + o]; __syncthreads(); }
    const float rstd = rsqrtf(red[0] * (1.0f / EE) + LNEPS);

    float* orow = out + (size_t)r * EE;
    for (int i = t; i < EE; i += 256)
        orow[i] = (row[i] - mean) * rstd * g[i] + b[i];
}

// ================= launcher =================
extern "C" void kernel_launch(void* const* d_in, const int* in_sizes, int n_in,
                              void* d_out, int out_size)
{
    (void)in_sizes; (void)n_in; (void)out_size;
    const float* x      = (const float*)d_in[0];
    const float* ln1_g  = (const float*)d_in[1];
    const float* ln1_b  = (const float*)d_in[2];
    const float* Wq     = (const float*)d_in[3];
    const float* Wk     = (const float*)d_in[4];
    const float* Wv     = (const float*)d_in[5];
    const float* proj_W = (const float*)d_in[6];
    const float* proj_b = (const float*)d_in[7];
    const float* ln2_g  = (const float*)d_in[8];
    const float* ln2_b  = (const float*)d_in[9];
    const float* fin_W  = (const float*)d_in[10];
    const float* fin_b  = (const float*)d_in[11];
    const float* hid_W  = (const float*)d_in[12];
    const float* hid_b  = (const float*)d_in[13];
    const float* fout_W = (const float*)d_in[14];
    const float* fout_b = (const float*)d_in[15];
    float* out = (float*)d_out;

    float *h, *x1;
    __nv_bfloat16 *sah, *sal, *sbh, *sbl, *wh, *wl, *qh, *ql, *kh, *kl, *vh, *vl;
    cudaGetSymbolAddress((void**)&h,   g_h);
    cudaGetSymbolAddress((void**)&x1,  g_x1);
    cudaGetSymbolAddress((void**)&sah, g_sah);
    cudaGetSymbolAddress((void**)&sal, g_sal);
    cudaGetSymbolAddress((void**)&sbh, g_sbh);
    cudaGetSymbolAddress((void**)&sbl, g_sbl);
    cudaGetSymbolAddress((void**)&wh,  g_wh);
    cudaGetSymbolAddress((void**)&wl,  g_wl);
    cudaGetSymbolAddress((void**)&qh,  g_qh);
    cudaGetSymbolAddress((void**)&ql,  g_ql);
    cudaGetSymbolAddress((void**)&kh,  g_kh);
    cudaGetSymbolAddress((void**)&kl,  g_kl);
    cudaGetSymbolAddress((void**)&vh,  g_vh);
    cudaGetSymbolAddress((void**)&vl,  g_vl);

    constexpr int SMG = 65536;     // gemm stages
    constexpr int SMF = 163840;    // flash: Q 32K + 2 x 64K
    cudaFuncSetAttribute((const void*)mma_gemm<false, false, false, true>,
                         cudaFuncAttributeMaxDynamicSharedMemorySize, SMG);
    cudaFuncSetAttribute((const void*)mma_gemm<true, false, true, false>,
                         cudaFuncAttributeMaxDynamicSharedMemorySize, SMG);
    cudaFuncSetAttribute((const void*)mma_gemm<true, true, false, true>,
                         cudaFuncAttributeMaxDynamicSharedMemorySize, SMG);
    cudaFuncSetAttribute((const void*)flash_kernel,
                         cudaFuncAttributeMaxDynamicSharedMemorySize, SMF);

    // ---------- attention ----------
    ln_kernel<<<MTOK, 256>>>(x, ln1_g, ln1_b, h);
    split_kernel<<<MTOK * EE / 1024, 256>>>(h, sah, sal, MTOK * EE);
    {
        dim3 g(KDIM / 32, EE / 32, HH);
        trsplit_kernel<<<g, 256>>>(Wq, wh, wl, EE, KDIM,
                                   (long long)EE * KDIM, (long long)KDIM * EE);
        trsplit_kernel<<<g, 256>>>(Wk, wh + (size_t)1024 * EE, wl + (size_t)1024 * EE,
                                   EE, KDIM, (long long)EE * KDIM, (long long)KDIM * EE);
        trsplit_kernel<<<g, 256>>>(Wv, wh + (size_t)2048 * EE, wl + (size_t)2048 * EE,
                                   EE, KDIM, (long long)EE * KDIM, (long long)KDIM * EE);
    }
    // QKV: [4096,1024] @ [3072,1024]^T -> split bf16 [t][3072]
    mma_gemm<false, false, false, true><<<dim3(3072 / 128, MTOK / 128), 256, SMG>>>(
        sah, sal, wh, wl, nullptr, nullptr, nullptr, sbh, sbl, MTOK, 3072, EE);
    qkv_reorder_bf<<<HH * MTOK * KDIM / 256, 256>>>(sbh, sbl, qh, ql, kh, kl, vh, vl);

    // fused causal attention -> split output in concat layout (sa buffers)
    flash_kernel<<<dim3(SS / 128, HH * BB), 256, SMF>>>(
        qh, ql, kh, kl, vh, vl, sah, sal);

    // x1 = x + o @ proj_W + proj_b
    trsplit_kernel<<<dim3(EE / 32, EE / 32, 1), 256>>>(proj_W, wh, wl, EE, EE, 0LL, 0LL);
    mma_gemm<true, false, true, false><<<dim3(EE / 128, MTOK / 128), 256, SMG>>>(
        sah, sal, wh, wl, proj_b, x, x1, nullptr, nullptr, MTOK, EE, EE);

    // ---------- FFN (split bf16 chain) ----------
    ln_kernel<<<MTOK, 256>>>(x1, ln2_g, ln2_b, h);
    split_kernel<<<MTOK * EE / 1024, 256>>>(h, sah, sal, MTOK * EE);

    trsplit_kernel<<<dim3(DD / 32, EE / 32, 1), 256>>>(fin_W, wh, wl, EE, DD, 0LL, 0LL);
    mma_gemm<true, true, false, true><<<dim3(DD / 128, MTOK / 128), 256, SMG>>>(
        sah, sal, wh, wl, fin_b, nullptr, nullptr, sbh, sbl, MTOK, DD, EE);

    trsplit_kernel<<<dim3(DD / 32, DD / 32, 1), 256>>>(hid_W, wh, wl, DD, DD, 0LL, 0LL);
    mma_gemm<true, true, false, true><<<dim3(DD / 128, MTOK / 128), 256, SMG>>>(
        sbh, sbl, wh, wl, hid_b, nullptr, nullptr, sah, sal, MTOK, DD, DD);

    trsplit_kernel<<<dim3(DD / 32, DD / 32, 1), 256>>>(
        hid_W + (size_t)DD * DD, wh, wl, DD, DD, 0LL, 0LL);
    mma_gemm<true, true, false, true><<<dim3(DD / 128, MTOK / 128), 256, SMG>>>(
        sah, sal, wh, wl, hid_b + DD, nullptr, nullptr, sbh, sbl, MTOK, DD, DD);

    trsplit_kernel<<<dim3(EE / 32, DD / 32, 1), 256>>>(fout_W, wh, wl, DD, EE, 0LL, 0LL);
    mma_gemm<true, false, true, false><<<dim3(EE / 128, MTOK / 128), 256, SMG>>>(
        sbh, sbl, wh, wl, fout_b, x1, out, nullptr, nullptr, MTOK, EE, DD);
}

// round 8
// speedup vs baseline: 3.2453x; 1.1211x over previous
#include <cuda_runtime.h>
#include <cuda_bf16.h>
#include <math.h>
#include <stdint.h>
#include <string.h>

// ---------------- problem constants ----------------
#define BB   4
#define SS   1024
#define EE   1024
#define HH   16
#define KDIM 64
#define VDIM 64
#define DD   4096
#define MTOK 4096            // B*S tokens
#define LNEPS 1e-5f

// ---------------- device scratch (static globals; no allocations) ----------------
__device__ float g_x1[MTOK * EE];
__device__ __nv_bfloat16 g_sah[(size_t)MTOK * DD];
__device__ __nv_bfloat16 g_sal[(size_t)MTOK * DD];
__device__ __nv_bfloat16 g_sbh[(size_t)MTOK * DD];
__device__ __nv_bfloat16 g_sbl[(size_t)MTOK * DD];
__device__ __nv_bfloat16 g_wh[(size_t)DD * DD];
__device__ __nv_bfloat16 g_wl[(size_t)DD * DD];
__device__ __nv_bfloat16 g_qh[HH * MTOK * KDIM];
__device__ __nv_bfloat16 g_ql[HH * MTOK * KDIM];
__device__ __nv_bfloat16 g_kh[HH * MTOK * KDIM];
__device__ __nv_bfloat16 g_kl[HH * MTOK * KDIM];
__device__ __nv_bfloat16 g_vh[HH * MTOK * VDIM];
__device__ __nv_bfloat16 g_vl[HH * MTOK * VDIM];

// ================= low-level helpers (sm_80+ base-target PTX only) =================
__device__ __forceinline__ uint32_t smem_to_u32(const void* p) {
    uint32_t a;
    asm("{ .reg .u64 t; cvta.to.shared.u64 t, %1; cvt.u32.u64 %0, t; }"
        : "=r"(a) : "l"(p));
    return a;
}
__device__ __forceinline__ void cp_async16(uint32_t dst, const void* src) {
    asm volatile("cp.async.cg.shared.global [%0], [%1], 16;"
                 :: "r"(dst), "l"(src) : "memory");
}
#define CP_COMMIT() asm volatile("cp.async.commit_group;" ::: "memory")
#define CP_WAIT(n)  asm volatile("cp.async.wait_group %0;" :: "n"(n) : "memory")

__device__ __forceinline__ void ldmatrix_x4(uint32_t& r0, uint32_t& r1,
                                            uint32_t& r2, uint32_t& r3, uint32_t addr) {
    asm volatile("ldmatrix.sync.aligned.m8n8.x4.shared.b16 {%0,%1,%2,%3}, [%4];"
                 : "=r"(r0), "=r"(r1), "=r"(r2), "=r"(r3) : "r"(addr));
}
__device__ __forceinline__ void ldmatrix_x4_trans(uint32_t& r0, uint32_t& r1,
                                                  uint32_t& r2, uint32_t& r3, uint32_t addr) {
    asm volatile("ldmatrix.sync.aligned.m8n8.x4.trans.shared.b16 {%0,%1,%2,%3}, [%4];"
                 : "=r"(r0), "=r"(r1), "=r"(r2), "=r"(r3) : "r"(addr));
}
__device__ __forceinline__ void mma_bf16(float* d, const uint32_t* a, const uint32_t* b) {
    asm volatile(
        "mma.sync.aligned.m16n8k16.row.col.f32.bf16.bf16.f32 "
        "{%0,%1,%2,%3}, {%4,%5,%6,%7}, {%8,%9}, {%0,%1,%2,%3};"
        : "+f"(d[0]), "+f"(d[1]), "+f"(d[2]), "+f"(d[3])
        : "r"(a[0]), "r"(a[1]), "r"(a[2]), "r"(a[3]), "r"(b[0]), "r"(b[1]));
}
__device__ __forceinline__ uint32_t pack_bf16x2(__nv_bfloat16 a, __nv_bfloat16 b) {
    return (uint32_t)__bfloat16_as_ushort(a) | ((uint32_t)__bfloat16_as_ushort(b) << 16);
}

// ================= split-bf16 tensor-core GEMM (HMMA path) =================
// C[M,N] = (Ah+Al)[M,K] @ (Bh+Bl)[N,K]^T (+bias)(+res)(relu).
// OSPLIT: write result as bf16 hi/lo pair instead of fp32.
// CTA tile 128 x 128, BK=64 (128B rows, XOR-8-group swizzle). 8 warps 4(M)x2(N).
// Single __syncthreads per K-chunk; loads issued after the barrier.
template<bool BIAS, bool RELU, bool RES, bool OSPLIT>
__global__ __launch_bounds__(256, 1) void mma_gemm(
    const __nv_bfloat16* __restrict__ Ah, const __nv_bfloat16* __restrict__ Al,
    const __nv_bfloat16* __restrict__ Bh, const __nv_bfloat16* __restrict__ Bl,
    const float* __restrict__ bias, const float* __restrict__ res,
    float* __restrict__ C, __nv_bfloat16* __restrict__ Ch,
    __nv_bfloat16* __restrict__ Cl, int M, int N, int K)
{
    constexpr int BM = 128, BN = 128, BK = 64;
    constexpr int NFRAG = BN / 16;              // 8
    constexpr int ASZ = BM * 128;               // 16384 bytes per matrix per stage
    constexpr int BSZ = BN * 128;
    constexpr int STAGE = 2 * ASZ + 2 * BSZ;    // 65536

    extern __shared__ char smem[];
    const uint32_t sb = smem_to_u32(smem);

    const int m0 = blockIdx.y * BM;
    const int n0 = blockIdx.x * BN;
    const int tid = threadIdx.x;
    const int lane = tid & 31;
    const int wid = tid >> 5;
    const int wm = wid >> 1;
    const int wn = wid & 1;

    auto load_stage = [&](int kc, int s) {
        const uint32_t st = sb + s * STAGE;
        const int koff = kc * BK;
#pragma unroll
        for (int i = 0; i < 4; i++) {           // A: 128 rows x 8 groups of 16B
            const int idx = tid + i * 256;
            const int row = idx >> 3, g = idx & 7;
            const uint32_t d = st + row * 128 + ((g ^ (row & 7)) << 4);
            const size_t src = (size_t)(m0 + row) * K + koff + g * 8;
            cp_async16(d,        Ah + src);
            cp_async16(d + ASZ,  Al + src);
        }
#pragma unroll
        for (int i = 0; i < 4; i++) {           // B: 128 rows x 8 groups
            const int idx = tid + i * 256;
            const int row = idx >> 3, g = idx & 7;
            const uint32_t d = st + 2 * ASZ + row * 128 + ((g ^ (row & 7)) << 4);
            const size_t src = (size_t)(n0 + row) * K + koff + g * 8;
            cp_async16(d,        Bh + src);
            cp_async16(d + BSZ,  Bl + src);
        }
    };

    float acc[2][NFRAG][4];
#pragma unroll
    for (int i = 0; i < 2; i++)
#pragma unroll
        for (int j = 0; j < NFRAG; j++)
#pragma unroll
            for (int c = 0; c < 4; c++) acc[i][j][c] = 0.f;

    const int KC = K / BK;
    load_stage(0, 0);
    CP_COMMIT();

    for (int kc = 0; kc < KC; kc++) {
        CP_WAIT(0);
        __syncthreads();                         // stage kc ready; prev buffer free
        if (kc + 1 < KC) {
            load_stage(kc + 1, (kc + 1) & 1);    // overlaps with compute below
            CP_COMMIT();
        }
        const uint32_t st = sb + (kc & 1) * STAGE;
#pragma unroll
        for (int ks = 0; ks < 4; ks++) {         // 4 x K=16 per chunk
            uint32_t afh[2][4], afl[2][4];
#pragma unroll
            for (int mf = 0; mf < 2; mf++) {
                const int row = wm * 32 + mf * 16 + (lane & 15);
                const int g = (ks * 2 + (lane >> 4)) ^ (row & 7);
                const uint32_t addr = st + row * 128 + (g << 4);
                ldmatrix_x4(afh[mf][0], afh[mf][1], afh[mf][2], afh[mf][3], addr);
                ldmatrix_x4(afl[mf][0], afl[mf][1], afl[mf][2], afl[mf][3], addr + ASZ);
            }
            uint32_t bfh[NFRAG][2], bfl[NFRAG][2];
#pragma unroll
            for (int nq = 0; nq < NFRAG / 2; nq++) {
                const int row = wn * (BN / 2) + nq * 16 + (lane & 15);
                const int g = (ks * 2 + (lane >> 4)) ^ (row & 7);
                const uint32_t addr = st + 2 * ASZ + row * 128 + (g << 4);
                uint32_t r0, r1, r2, r3;
                ldmatrix_x4(r0, r1, r2, r3, addr);
                bfh[2 * nq][0] = r0; bfh[2 * nq][1] = r2;
                bfh[2 * nq + 1][0] = r1; bfh[2 * nq + 1][1] = r3;
                ldmatrix_x4(r0, r1, r2, r3, addr + BSZ);
                bfl[2 * nq][0] = r0; bfl[2 * nq][1] = r2;
                bfl[2 * nq + 1][0] = r1; bfl[2 * nq + 1][1] = r3;
            }
#pragma unroll
            for (int mf = 0; mf < 2; mf++)
#pragma unroll
                for (int nf = 0; nf < NFRAG; nf++) {
                    mma_bf16(acc[mf][nf], afh[mf], bfh[nf]);
                    mma_bf16(acc[mf][nf], afh[mf], bfl[nf]);
                    mma_bf16(acc[mf][nf], afl[mf], bfh[nf]);
                }
        }
        __syncthreads();                         // done reading stage kc
    }

    // ---- epilogue ----
#pragma unroll
    for (int mf = 0; mf < 2; mf++) {
        const int r0i = m0 + wm * 32 + mf * 16 + (lane >> 2);
#pragma unroll
        for (int nf = 0; nf < NFRAG; nf++) {
            const int col = n0 + wn * (BN / 2) + nf * 8 + (lane & 3) * 2;
            float2 bv = make_float2(0.f, 0.f);
            if (BIAS) { bv.x = bias[col]; bv.y = bias[col + 1]; }
#pragma unroll
            for (int hrow = 0; hrow < 2; hrow++) {
                const int rr = r0i + hrow * 8;
                float2 v;
                v.x = acc[mf][nf][2 * hrow + 0] + bv.x;
                v.y = acc[mf][nf][2 * hrow + 1] + bv.y;
                if (RES) {
                    const float2 rv = *(const float2*)(res + (size_t)rr * N + col);
                    v.x += rv.x; v.y += rv.y;
                }
                if (RELU) { v.x = fmaxf(v.x, 0.f); v.y = fmaxf(v.y, 0.f); }
                if (OSPLIT) {
                    const __nv_bfloat16 h0 = __float2bfloat16(v.x);
                    const __nv_bfloat16 h1 = __float2bfloat16(v.y);
                    const __nv_bfloat16 l0 = __float2bfloat16(v.x - __bfloat162float(h0));
                    const __nv_bfloat16 l1 = __float2bfloat16(v.y - __bfloat162float(h1));
                    *(uint32_t*)(Ch + (size_t)rr * N + col) = pack_bf16x2(h0, h1);
                    *(uint32_t*)(Cl + (size_t)rr * N + col) = pack_bf16x2(l0, l1);
                } else {
                    *(float2*)(C + (size_t)rr * N + col) = v;
                }
            }
        }
    }
}

// ================= flash attention (causal, faithful ==0 mask) =================
// grid (qt=8, hb=64); block 256 = 8 warps, warp w owns rows [16w,16w+16).
// q/k/v split bf16 [hb][S][64]; output split bf16 in concat layout [token][EE].
__global__ __launch_bounds__(256, 1) void flash_kernel(
    const __nv_bfloat16* __restrict__ qh, const __nv_bfloat16* __restrict__ ql,
    const __nv_bfloat16* __restrict__ kh, const __nv_bfloat16* __restrict__ kl,
    const __nv_bfloat16* __restrict__ vh, const __nv_bfloat16* __restrict__ vl,
    __nv_bfloat16* __restrict__ oh, __nv_bfloat16* __restrict__ ol)
{
    extern __shared__ char smem[];
    const uint32_t sb = smem_to_u32(smem);
    const int qt = blockIdx.x;
    const int hb = blockIdx.y;
    const int tid = threadIdx.x, lane = tid & 31, w = tid >> 5;

    const size_t hbase = (size_t)hb * SS * 64;
    const __nv_bfloat16* Qh = qh + hbase + (size_t)qt * 128 * 64;
    const __nv_bfloat16* Ql = ql + hbase + (size_t)qt * 128 * 64;
    const __nv_bfloat16* Kh = kh + hbase;
    const __nv_bfloat16* Kl = kl + hbase;
    const __nv_bfloat16* Vh = vh + hbase;
    const __nv_bfloat16* Vl = vl + hbase;

    // SMEM: [0,16K) Qh, [16K,32K) Ql; stage s at 32768+s*65536: Kh|Kl|Vh|Vl 16K each
#pragma unroll
    for (int i = 0; i < 4; i++) {
        const int idx = tid + i * 256;
        const int row = idx >> 3, g = idx & 7;
        const uint32_t off = row * 128 + ((g ^ (row & 7)) << 4);
        const size_t src = (size_t)row * 64 + g * 8;
        cp_async16(sb + off,         Qh + src);
        cp_async16(sb + 16384 + off, Ql + src);
    }
    auto load_kv = [&](int jt, int s) {
        const uint32_t st = sb + 32768 + s * 65536;
        const size_t base = (size_t)jt * 128 * 64;
#pragma unroll
        for (int i = 0; i < 4; i++) {
            const int idx = tid + i * 256;
            const int row = idx >> 3, g = idx & 7;
            const uint32_t off = row * 128 + ((g ^ (row & 7)) << 4);
            const size_t src = base + (size_t)row * 64 + g * 8;
            cp_async16(st + off,         Kh + src);
            cp_async16(st + 16384 + off, Kl + src);
            cp_async16(st + 32768 + off, Vh + src);
            cp_async16(st + 49152 + off, Vl + src);
        }
    };
    load_kv(0, 0);
    CP_COMMIT();

    uint32_t qfh[4][4], qfl[4][4];
    float ofr[8][4];
    float mrow[2] = {-INFINITY, -INFINITY};
    float lrow[2] = {0.f, 0.f};
#pragma unroll
    for (int f = 0; f < 8; f++)
#pragma unroll
        for (int c = 0; c < 4; c++) ofr[f][c] = 0.f;

    const int rb = qt * 128 + w * 16 + (lane >> 2);

    for (int jt = 0; jt <= qt; jt++) {
        if (jt < qt) { load_kv(jt + 1, (jt + 1) & 1); CP_COMMIT(); CP_WAIT(1); }
        else CP_WAIT(0);
        __syncthreads();

        if (jt == 0) {
#pragma unroll
            for (int kk = 0; kk < 4; kk++) {
                const int row = w * 16 + (lane & 15);
                const uint32_t c = (uint32_t)((kk * 2 + (lane >> 4)) ^ (row & 7));
                const uint32_t addr = sb + row * 128 + (c << 4);
                ldmatrix_x4(qfh[kk][0], qfh[kk][1], qfh[kk][2], qfh[kk][3], addr);
                ldmatrix_x4(qfl[kk][0], qfl[kk][1], qfl[kk][2], qfl[kk][3], addr + 16384);
            }
        }

        const uint32_t st = sb + 32768 + (jt & 1) * 65536;

        // ---- S = Q K^T (split: hh + hl + lh) ----
        float cfr[16][4];
#pragma unroll
        for (int f = 0; f < 16; f++)
#pragma unroll
            for (int c = 0; c < 4; c++) cfr[f][c] = 0.f;

#pragma unroll
        for (int kk = 0; kk < 4; kk++) {
#pragma unroll
            for (int nq = 0; nq < 8; nq++) {
                const int row = nq * 16 + (lane & 15);
                const uint32_t c = (uint32_t)((kk * 2 + (lane >> 4)) ^ (row & 7));
                const uint32_t addr = st + row * 128 + (c << 4);
                uint32_t r0, r1, r2, r3, s0, s1, s2, s3;
                ldmatrix_x4(r0, r1, r2, r3, addr);
                ldmatrix_x4(s0, s1, s2, s3, addr + 16384);
                uint32_t bh0[2] = {r0, r2}, bh1[2] = {r1, r3};
                uint32_t bl0[2] = {s0, s2}, bl1[2] = {s1, s3};
                mma_bf16(cfr[2 * nq],     qfh[kk], bh0);
                mma_bf16(cfr[2 * nq],     qfh[kk], bl0);
                mma_bf16(cfr[2 * nq],     qfl[kk], bh0);
                mma_bf16(cfr[2 * nq + 1], qfh[kk], bh1);
                mma_bf16(cfr[2 * nq + 1], qfh[kk], bl1);
                mma_bf16(cfr[2 * nq + 1], qfl[kk], bh1);
            }
        }

        // ---- mask + scale + row max ----
        float tm[2] = {-INFINITY, -INFINITY};
#pragma unroll
        for (int f = 0; f < 16; f++) {
            const int col = jt * 128 + f * 8 + (lane & 3) * 2;
#pragma unroll
            for (int h2 = 0; h2 < 2; h2++) {
                const int rg = rb + h2 * 8;
                float v0 = cfr[f][2 * h2], v1 = cfr[f][2 * h2 + 1];
                v0 = (v0 == 0.f || col > rg)     ? -INFINITY : v0 * 0.125f;
                v1 = (v1 == 0.f || col + 1 > rg) ? -INFINITY : v1 * 0.125f;
                cfr[f][2 * h2] = v0; cfr[f][2 * h2 + 1] = v1;
                tm[h2] = fmaxf(tm[h2], fmaxf(v0, v1));
            }
        }
#pragma unroll
        for (int h2 = 0; h2 < 2; h2++) {
            tm[h2] = fmaxf(tm[h2], __shfl_xor_sync(0xffffffffu, tm[h2], 1));
            tm[h2] = fmaxf(tm[h2], __shfl_xor_sync(0xffffffffu, tm[h2], 2));
            const float mn = fmaxf(mrow[h2], tm[h2]);
            const float alpha = __expf(mrow[h2] - mn);
            mrow[h2] = mn;
            lrow[h2] *= alpha;
#pragma unroll
            for (int f = 0; f < 8; f++) {
                ofr[f][2 * h2]     *= alpha;
                ofr[f][2 * h2 + 1] *= alpha;
            }
        }
        // ---- exponentiate + row sum ----
        float rs[2] = {0.f, 0.f};
#pragma unroll
        for (int f = 0; f < 16; f++) {
#pragma unroll
            for (int h2 = 0; h2 < 2; h2++) {
                const float p0 = __expf(cfr[f][2 * h2]     - mrow[h2]);
                const float p1 = __expf(cfr[f][2 * h2 + 1] - mrow[h2]);
                cfr[f][2 * h2] = p0; cfr[f][2 * h2 + 1] = p1;
                rs[h2] += p0 + p1;
            }
        }
#pragma unroll
        for (int h2 = 0; h2 < 2; h2++) {
            rs[h2] += __shfl_xor_sync(0xffffffffu, rs[h2], 1);
            rs[h2] += __shfl_xor_sync(0xffffffffu, rs[h2], 2);
            lrow[h2] += rs[h2];
        }

        // ---- O += P V (P split in registers; V split from SMEM via trans) ----
#pragma unroll
        for (int kk2 = 0; kk2 < 8; kk2++) {
            uint32_t pah[4], pal[4];
#pragma unroll
            for (int r = 0; r < 4; r++) {
                const int f = 2 * kk2 + (r >> 1);
                const int c0 = (r & 1) * 2;
                const float f0 = cfr[f][c0], f1 = cfr[f][c0 + 1];
                const __nv_bfloat16 h0 = __float2bfloat16(f0);
                const __nv_bfloat16 h1 = __float2bfloat16(f1);
                const __nv_bfloat16 l0 = __float2bfloat16(f0 - __bfloat162float(h0));
                const __nv_bfloat16 l1 = __float2bfloat16(f1 - __bfloat162float(h1));
                pah[r] = pack_bf16x2(h0, h1);
                pal[r] = pack_bf16x2(l0, l1);
            }
#pragma unroll
            for (int of2 = 0; of2 < 4; of2++) {
                const int row = kk2 * 16 + (lane & 15);
                const uint32_t c = (uint32_t)((of2 * 2 + (lane >> 4)) ^ (row & 7));
                const uint32_t addr = st + 32768 + row * 128 + (c << 4);
                uint32_t d0, d1, d2, d3, e0, e1, e2, e3;
                ldmatrix_x4_trans(d0, d1, d2, d3, addr);
                ldmatrix_x4_trans(e0, e1, e2, e3, addr + 16384);
                uint32_t v0h[2] = {d0, d1}, v1h[2] = {d2, d3};
                uint32_t v0l[2] = {e0, e1}, v1l[2] = {e2, e3};
                mma_bf16(ofr[2 * of2],     pah, v0h);
                mma_bf16(ofr[2 * of2],     pah, v0l);
                mma_bf16(ofr[2 * of2],     pal, v0h);
                mma_bf16(ofr[2 * of2 + 1], pah, v1h);
                mma_bf16(ofr[2 * of2 + 1], pah, v1l);
                mma_bf16(ofr[2 * of2 + 1], pal, v1h);
            }
        }
        __syncthreads();
    }

    // ---- finalize: O /= l, write split bf16 in concat layout ----
    const float inv0 = 1.f / lrow[0], inv1 = 1.f / lrow[1];
    const int hI = hb >> 2, bI = hb & 3;
    const int s0 = qt * 128 + w * 16 + (lane >> 2);
#pragma unroll
    for (int f = 0; f < 8; f++) {
        const int col = hI * 64 + f * 8 + (lane & 3) * 2;
#pragma unroll
        for (int h2 = 0; h2 < 2; h2++) {
            const int token = bI * SS + s0 + h2 * 8;
            const float inv = h2 ? inv1 : inv0;
            const float a = ofr[f][2 * h2] * inv;
            const float b = ofr[f][2 * h2 + 1] * inv;
            const __nv_bfloat16 h0 = __float2bfloat16(a);
            const __nv_bfloat16 h1 = __float2bfloat16(b);
            const __nv_bfloat16 l0 = __float2bfloat16(a - __bfloat162float(h0));
            const __nv_bfloat16 l1 = __float2bfloat16(b - __bfloat162float(h1));
            *(uint32_t*)(oh + (size_t)token * EE + col) = pack_bf16x2(h0, h1);
            *(uint32_t*)(ol + (size_t)token * EE + col) = pack_bf16x2(l0, l1);
        }
    }
}

// ================= fused LayerNorm -> split bf16 =================
__global__ __launch_bounds__(256) void ln_split_kernel(
    const float* __restrict__ x, const float* __restrict__ g,
    const float* __restrict__ b, __nv_bfloat16* __restrict__ hi,
    __nv_bfloat16* __restrict__ lo)
{
    __shared__ float row[EE];
    __shared__ float red[256];
    const int r = blockIdx.x;
    const int t = threadIdx.x;
    const float* xr = x + (size_t)r * EE;

    float s = 0.f;
    for (int i = t; i < EE; i += 256) { float v = xr[i]; row[i] = v; s += v; }
    red[t] = s; __syncthreads();
    for (int o = 128; o > 0; o >>= 1) { if (t < o) red[t] += red[t + o]; __syncthreads(); }
    const float mean = red[0] * (1.0f / EE);
    __syncthreads();

    float vs = 0.f;
    for (int i = t; i < EE; i += 256) { float d = row[i] - mean; vs += d * d; }
    red[t] = vs; __syncthreads();
    for (int o = 128; o > 0; o >>= 1) { if (t < o) red[t] += red[t + o]; __syncthreads(); }
    const float rstd = rsqrtf(red[0] * (1.0f / EE) + LNEPS);

    __nv_bfloat16* hrow = hi + (size_t)r * EE;
    __nv_bfloat16* lrow = lo + (size_t)r * EE;
    for (int i = t; i < EE; i += 256) {
        const float v = (row[i] - mean) * rstd * g[i] + b[i];
        const __nv_bfloat16 h = __float2bfloat16(v);
        hrow[i] = h;
        lrow[i] = __float2bfloat16(v - __bfloat162float(h));
    }
}

// fp32 W[R,C] -> bf16 split transpose Th/Tl[C,R]; batched over z with strides
__global__ __launch_bounds__(256) void trsplit_kernel(
    const float* __restrict__ W, __nv_bfloat16* __restrict__ Th,
    __nv_bfloat16* __restrict__ Tl, int R, int C, long long sIn, long long sOut)
{
    __shared__ float t[32][33];
    const int z = blockIdx.z;
    W  += (long long)z * sIn;
    Th += (long long)z * sOut;
    Tl += (long long)z * sOut;
    const int r0 = blockIdx.y * 32, c0 = blockIdx.x * 32;
    const int tx = threadIdx.x & 31, ty = threadIdx.x >> 5;
#pragma unroll
    for (int i = 0; i < 32; i += 8)
        t[ty + i][tx] = W[(long long)(r0 + ty + i) * C + c0 + tx];
    __syncthreads();
#pragma unroll
    for (int i = 0; i < 32; i += 8) {
        const float v = t[tx][ty + i];
        const __nv_bfloat16 h = __float2bfloat16(v);
        const __nv_bfloat16 l = __float2bfloat16(v - __bfloat162float(h));
        const long long o = (long long)(c0 + ty + i) * R + r0 + tx;
        Th[o] = h; Tl[o] = l;
    }
}

// split QKV GEMM output [t][3072] -> q/k/v [hb][s][64] (hb = h*BB + b, t = b*SS + s)
__global__ __launch_bounds__(256) void qkv_reorder_bf(
    const __nv_bfloat16* __restrict__ sh, const __nv_bfloat16* __restrict__ sl,
    __nv_bfloat16* __restrict__ qh, __nv_bfloat16* __restrict__ ql,
    __nv_bfloat16* __restrict__ kh, __nv_bfloat16* __restrict__ kl,
    __nv_bfloat16* __restrict__ vh, __nv_bfloat16* __restrict__ vl)
{
    const int idx = blockIdx.x * 256 + threadIdx.x;
    const int kd = idx & 63;
    const int t  = (idx >> 6) & (MTOK - 1);
    const int h  = idx >> 18;
    const size_t src = (size_t)t * 3072 + h * 64 + kd;
    qh[idx] = sh[src];          ql[idx] = sl[src];
    kh[idx] = sh[src + 1024];   kl[idx] = sl[src + 1024];
    vh[idx] = sh[src + 2048];   vl[idx] = sl[src + 2048];
}

// ================= launcher =================
extern "C" void kernel_launch(void* const* d_in, const int* in_sizes, int n_in,
                              void* d_out, int out_size)
{
    (void)in_sizes; (void)n_in; (void)out_size;
    const float* x      = (const float*)d_in[0];
    const float* ln1_g  = (const float*)d_in[1];
    const float* ln1_b  = (const float*)d_in[2];
    const float* Wq     = (const float*)d_in[3];
    const float* Wk     = (const float*)d_in[4];
    const float* Wv     = (const float*)d_in[5];
    const float* proj_W = (const float*)d_in[6];
    const float* proj_b = (const float*)d_in[7];
    const float* ln2_g  = (const float*)d_in[8];
    const float* ln2_b  = (const float*)d_in[9];
    const float* fin_W  = (const float*)d_in[10];
    const float* fin_b  = (const float*)d_in[11];
    const float* hid_W  = (const float*)d_in[12];
    const float* hid_b  = (const float*)d_in[13];
    const float* fout_W = (const float*)d_in[14];
    const float* fout_b = (const float*)d_in[15];
    float* out = (float*)d_out;

    float *x1;
    __nv_bfloat16 *sah, *sal, *sbh, *sbl, *wh, *wl, *qh, *ql, *kh, *kl, *vh, *vl;
    cudaGetSymbolAddress((void**)&x1,  g_x1);
    cudaGetSymbolAddress((void**)&sah, g_sah);
    cudaGetSymbolAddress((void**)&sal, g_sal);
    cudaGetSymbolAddress((void**)&sbh, g_sbh);
    cudaGetSymbolAddress((void**)&sbl, g_sbl);
    cudaGetSymbolAddress((void**)&wh,  g_wh);
    cudaGetSymbolAddress((void**)&wl,  g_wl);
    cudaGetSymbolAddress((void**)&qh,  g_qh);
    cudaGetSymbolAddress((void**)&ql,  g_ql);
    cudaGetSymbolAddress((void**)&kh,  g_kh);
    cudaGetSymbolAddress((void**)&kl,  g_kl);
    cudaGetSymbolAddress((void**)&vh,  g_vh);
    cudaGetSymbolAddress((void**)&vl,  g_vl);

    constexpr int SMG = 131072;    // gemm: 2 stages x 64KB
    constexpr int SMF = 163840;    // flash: Q 32K + 2 x 64K
    cudaFuncSetAttribute((const void*)mma_gemm<false, false, false, true>,
                         cudaFuncAttributeMaxDynamicSharedMemorySize, SMG);
    cudaFuncSetAttribute((const void*)mma_gemm<true, false, true, false>,
                         cudaFuncAttributeMaxDynamicSharedMemorySize, SMG);
    cudaFuncSetAttribute((const void*)mma_gemm<true, true, false, true>,
                         cudaFuncAttributeMaxDynamicSharedMemorySize, SMG);
    cudaFuncSetAttribute((const void*)flash_kernel,
                         cudaFuncAttributeMaxDynamicSharedMemorySize, SMF);

    // ---------- attention ----------
    ln_split_kernel<<<MTOK, 256>>>(x, ln1_g, ln1_b, sah, sal);
    {
        dim3 g(KDIM / 32, EE / 32, HH);
        trsplit_kernel<<<g, 256>>>(Wq, wh, wl, EE, KDIM,
                                   (long long)EE * KDIM, (long long)KDIM * EE);
        trsplit_kernel<<<g, 256>>>(Wk, wh + (size_t)1024 * EE, wl + (size_t)1024 * EE,
                                   EE, KDIM, (long long)EE * KDIM, (long long)KDIM * EE);
        trsplit_kernel<<<g, 256>>>(Wv, wh + (size_t)2048 * EE, wl + (size_t)2048 * EE,
                                   EE, KDIM, (long long)EE * KDIM, (long long)KDIM * EE);
    }
    // QKV: [4096,1024] @ [3072,1024]^T -> split bf16 [t][3072]
    mma_gemm<false, false, false, true><<<dim3(3072 / 128, MTOK / 128), 256, SMG>>>(
        sah, sal, wh, wl, nullptr, nullptr, nullptr, sbh, sbl, MTOK, 3072, EE);
    qkv_reorder_bf<<<HH * MTOK * KDIM / 256, 256>>>(sbh, sbl, qh, ql, kh, kl, vh, vl);

    // fused causal attention -> split output in concat layout (sa buffers)
    flash_kernel<<<dim3(SS / 128, HH * BB), 256, SMF>>>(
        qh, ql, kh, kl, vh, vl, sah, sal);

    // x1 = x + o @ proj_W + proj_b
    trsplit_kernel<<<dim3(EE / 32, EE / 32, 1), 256>>>(proj_W, wh, wl, EE, EE, 0LL, 0LL);
    mma_gemm<true, false, true, false><<<dim3(EE / 128, MTOK / 128), 256, SMG>>>(
        sah, sal, wh, wl, proj_b, x, x1, nullptr, nullptr, MTOK, EE, EE);

    // ---------- FFN (split bf16 chain) ----------
    ln_split_kernel<<<MTOK, 256>>>(x1, ln2_g, ln2_b, sah, sal);

    trsplit_kernel<<<dim3(DD / 32, EE / 32, 1), 256>>>(fin_W, wh, wl, EE, DD, 0LL, 0LL);
    mma_gemm<true, true, false, true><<<dim3(DD / 128, MTOK / 128), 256, SMG>>>(
        sah, sal, wh, wl, fin_b, nullptr, nullptr, sbh, sbl, MTOK, DD, EE);

    trsplit_kernel<<<dim3(DD / 32, DD / 32, 1), 256>>>(hid_W, wh, wl, DD, DD, 0LL, 0LL);
    mma_gemm<true, true, false, true><<<dim3(DD / 128, MTOK / 128), 256, SMG>>>(
        sbh, sbl, wh, wl, hid_b, nullptr, nullptr, sah, sal, MTOK, DD, DD);

    trsplit_kernel<<<dim3(DD / 32, DD / 32, 1), 256>>>(
        hid_W + (size_t)DD * DD, wh, wl, DD, DD, 0LL, 0LL);
    mma_gemm<true, true, false, true><<<dim3(DD / 128, MTOK / 128), 256, SMG>>>(
        sah, sal, wh, wl, hid_b + DD, nullptr, nullptr, sbh, sbl, MTOK, DD, DD);

    trsplit_kernel<<<dim3(EE / 32, DD / 32, 1), 256>>>(fout_W, wh, wl, DD, EE, 0LL, 0LL);
    mma_gemm<true, false, true, false><<<dim3(EE / 128, MTOK / 128), 256, SMG>>>(
        sbh, sbl, wh, wl, fout_b, x1, out, nullptr, nullptr, MTOK, EE, DD);
}